// round 8
// baseline (speedup 1.0000x reference)
#include <cuda_runtime.h>
#include <cuda_bf16.h>
#include <math.h>
#include <cstdint>

// ---------------- problem constants ----------------
#define L       2048
#define D       768
#define ED      1536
#define NL      4
#define NST     16
#define DTR     48
#define DXP     80
#define VOCAB   32000
#define DCONV   4
#define CHUNK   64
#define NCHUNK  (L / CHUNK)

// ---------------- scratch ----------------
__device__ __align__(256) float g_x    [L * D];
__device__ __align__(256) float g_xz   [L * 2 * ED];
__device__ __align__(256) float g_xb   [L * ED];
__device__ __align__(256) float g_dbc  [L * DXP];
__device__ __align__(256) float g_delta[L * ED];
__device__ __align__(256) float g_cp   [NCHUNK * ED * NST];
__device__ __align__(256) float g_cs   [NCHUNK * ED * NST];
__device__ __align__(256) float g_cc   [NCHUNK * ED * NST];
__device__ __align__(256) __nv_bfloat16 g_ah[L * ED];
__device__ __align__(256) __nv_bfloat16 g_al[L * ED];
__device__ __align__(256) __nv_bfloat16 g_dh[L * 64];
__device__ __align__(256) __nv_bfloat16 g_dl[L * 64];
__device__ __align__(256) __nv_bfloat16 g_wh[2 * ED * D];
__device__ __align__(256) __nv_bfloat16 g_wl[2 * ED * D];
// int8 path (lm_head)
__device__ __align__(256) int8_t g_qa1[L * D];
__device__ __align__(256) int8_t g_qa2[L * D];
__device__ __align__(256) int8_t g_qb1[VOCAB * D];
__device__ __align__(256) int8_t g_qb2[VOCAB * D];
__device__ __align__(256) float  g_sa[L];
__device__ __align__(256) float  g_sb[VOCAB];

// ---------------- helpers ----------------
__device__ __forceinline__ uint32_t smem_u32(const void* p) {
    uint32_t a;
    asm("{ .reg .u64 t; cvta.to.shared.u64 t, %1; cvt.u32.u64 %0, t; }" : "=r"(a) : "l"(p));
    return a;
}
__device__ __forceinline__ void ldsm4(uint32_t* r, uint32_t addr) {
    asm volatile("ldmatrix.sync.aligned.m8n8.x4.shared.b16 {%0,%1,%2,%3}, [%4];"
                 : "=r"(r[0]), "=r"(r[1]), "=r"(r[2]), "=r"(r[3]) : "r"(addr));
}
__device__ __forceinline__ void mma_bf16(float* d, const uint32_t* a, const uint32_t* b) {
    asm volatile(
        "mma.sync.aligned.m16n8k16.row.col.f32.bf16.bf16.f32 "
        "{%0,%1,%2,%3}, {%4,%5,%6,%7}, {%8,%9}, {%0,%1,%2,%3};"
        : "+f"(d[0]), "+f"(d[1]), "+f"(d[2]), "+f"(d[3])
        : "r"(a[0]), "r"(a[1]), "r"(a[2]), "r"(a[3]), "r"(b[0]), "r"(b[1]));
}
__device__ __forceinline__ void mma_s8(int* d, const uint32_t* a, const uint32_t* b) {
    asm volatile(
        "mma.sync.aligned.m16n8k32.row.col.s32.s8.s8.s32 "
        "{%0,%1,%2,%3}, {%4,%5,%6,%7}, {%8,%9}, {%0,%1,%2,%3};"
        : "+r"(d[0]), "+r"(d[1]), "+r"(d[2]), "+r"(d[3])
        : "r"(a[0]), "r"(a[1]), "r"(a[2]), "r"(a[3]), "r"(b[0]), "r"(b[1]));
}
__device__ __forceinline__ void cpa16(uint32_t d, const void* s) {
    asm volatile("cp.async.cg.shared.global [%0], [%1], 16;" :: "r"(d), "l"(s));
}
#define CP_COMMIT() asm volatile("cp.async.commit_group;" ::: "memory")
#define CP_WAIT0()  asm volatile("cp.async.wait_group 0;" ::: "memory")

// ---------------- embedding ----------------
__global__ void embed_k(const int* __restrict__ tok, const float* __restrict__ emb,
                        float* __restrict__ x) {
    int i = blockIdx.x * blockDim.x + threadIdx.x;
    if (i >= L * D) return;
    int t = i / D, d = i % D;
    x[i] = emb[(size_t)tok[t] * D + d];
}

// ---------------- fp32 -> bf16 hi/lo split ----------------
__global__ void split4_k(const float4* __restrict__ src, __nv_bfloat162* __restrict__ hi,
                         __nv_bfloat162* __restrict__ lo, int n4) {
    int i = blockIdx.x * blockDim.x + threadIdx.x;
    if (i >= n4) return;
    float4 v = src[i];
    __nv_bfloat16 hx = __float2bfloat16(v.x), hy = __float2bfloat16(v.y);
    __nv_bfloat16 hz = __float2bfloat16(v.z), hw = __float2bfloat16(v.w);
    hi[2 * i]     = __nv_bfloat162(hx, hy);
    hi[2 * i + 1] = __nv_bfloat162(hz, hw);
    lo[2 * i]     = __nv_bfloat162(__float2bfloat16(v.x - __bfloat162float(hx)),
                                   __float2bfloat16(v.y - __bfloat162float(hy)));
    lo[2 * i + 1] = __nv_bfloat162(__float2bfloat16(v.z - __bfloat162float(hz)),
                                   __float2bfloat16(v.w - __bfloat162float(hw)));
}

// padded split
__global__ void split_pad_k(const float* __restrict__ src, __nv_bfloat16* __restrict__ hi,
                            __nv_bfloat16* __restrict__ lo,
                            int Mdst, int Kp, int Msrc, int Kin, int Ssrc) {
    int i = blockIdx.x * blockDim.x + threadIdx.x;
    if (i >= Mdst * Kp) return;
    int r = i / Kp, c = i % Kp;
    float v = (r < Msrc && c < Kin) ? src[(size_t)r * Ssrc + c] : 0.f;
    __nv_bfloat16 h = __float2bfloat16(v);
    hi[i] = h;
    lo[i] = __float2bfloat16(v - __bfloat162float(h));
}

// ---------------- RMSNorm -> bf16 hi/lo ----------------
__global__ void rmsnorm_split_k(const float* __restrict__ x, const float* __restrict__ w,
                                __nv_bfloat16* __restrict__ oh, __nv_bfloat16* __restrict__ ol) {
    int t = blockIdx.x;
    const float* xr = x + (size_t)t * D;
    float s = 0.f;
    for (int d = threadIdx.x; d < D; d += 256) { float v = xr[d]; s += v * v; }
    __shared__ float red[256];
    red[threadIdx.x] = s;
    __syncthreads();
    for (int o = 128; o > 0; o >>= 1) {
        if (threadIdx.x < o) red[threadIdx.x] += red[threadIdx.x + o];
        __syncthreads();
    }
    float inv = rsqrtf(red[0] / (float)D + 1e-5f);
    for (int d = threadIdx.x; d < D; d += 256) {
        float v = xr[d] * inv * w[d];
        __nv_bfloat16 h = __float2bfloat16(v);
        oh[(size_t)t * D + d] = h;
        ol[(size_t)t * D + d] = __float2bfloat16(v - __bfloat162float(h));
    }
}

// ---------------- RMSNorm -> int8 2-digit (for lm_head A) ----------------
__global__ void rmsnorm_quant_k(const float* __restrict__ x, const float* __restrict__ w,
                                int8_t* __restrict__ q1, int8_t* __restrict__ q2,
                                float* __restrict__ sc) {
    int t = blockIdx.x;
    const float* xr = x + (size_t)t * D;
    float s = 0.f, mx = 0.f;
    for (int d = threadIdx.x; d < D; d += 256) {
        float v = xr[d];
        s += v * v;
        mx = fmaxf(mx, fabsf(v * w[d]));
    }
    __shared__ float rs[256], rm[256];
    rs[threadIdx.x] = s; rm[threadIdx.x] = mx;
    __syncthreads();
    for (int o = 128; o > 0; o >>= 1) {
        if (threadIdx.x < o) {
            rs[threadIdx.x] += rs[threadIdx.x + o];
            rm[threadIdx.x] = fmaxf(rm[threadIdx.x], rm[threadIdx.x + o]);
        }
        __syncthreads();
    }
    float inv = rsqrtf(rs[0] / (float)D + 1e-5f);
    float smax = rm[0] * inv;
    if (smax < 1e-30f) smax = 1e-30f;
    if (threadIdx.x == 0) sc[t] = smax;
    float k1 = 127.f / smax, k1i = smax / 127.f;
    for (int d = threadIdx.x; d < D; d += 256) {
        float v = xr[d] * inv * w[d];
        float a = rintf(v * k1);
        a = fminf(fmaxf(a, -127.f), 127.f);
        float r = fmaf(-a, k1i, v);
        float b = rintf(r * k1 * 128.f);
        b = fminf(fmaxf(b, -127.f), 127.f);
        q1[(size_t)t * D + d] = (int8_t)a;
        q2[(size_t)t * D + d] = (int8_t)b;
    }
}

// ---------------- per-row int8 2-digit quant (for lm_head B) ----------------
__global__ void quant_rows_k(const float* __restrict__ src, int Krow,
                             int8_t* __restrict__ q1, int8_t* __restrict__ q2,
                             float* __restrict__ sc) {
    int r = blockIdx.x;
    const float* row = src + (size_t)r * Krow;
    float mx = 0.f;
    for (int d = threadIdx.x; d < Krow; d += 128) mx = fmaxf(mx, fabsf(row[d]));
    __shared__ float rm[128];
    rm[threadIdx.x] = mx;
    __syncthreads();
    for (int o = 64; o > 0; o >>= 1) {
        if (threadIdx.x < o) rm[threadIdx.x] = fmaxf(rm[threadIdx.x], rm[threadIdx.x + o]);
        __syncthreads();
    }
    float smax = rm[0];
    if (smax < 1e-30f) smax = 1e-30f;
    if (threadIdx.x == 0) sc[r] = smax;
    float k1 = 127.f / smax, k1i = smax / 127.f;
    for (int d = threadIdx.x; d < Krow; d += 128) {
        float v = row[d];
        float a = rintf(v * k1);
        a = fminf(fmaxf(a, -127.f), 127.f);
        float rr = fmaf(-a, k1i, v);
        float b = rintf(rr * k1 * 128.f);
        b = fminf(fmaxf(b, -127.f), 127.f);
        q1[(size_t)r * Krow + d] = (int8_t)a;
        q2[(size_t)r * Krow + d] = (int8_t)b;
    }
}

// ---------------- conv1d + silu, fused bf16 hi/lo split of output ----------------
__global__ void conv_silu_split_k(const float* __restrict__ xz, const float* __restrict__ w,
                                  const float* __restrict__ b, float* __restrict__ xb,
                                  __nv_bfloat16* __restrict__ oh, __nv_bfloat16* __restrict__ ol) {
    int i = blockIdx.x * blockDim.x + threadIdx.x;
    if (i >= L * ED) return;
    int t = i / ED, e = i % ED;
    const float* wr = w + e * DCONV;
    float acc = b[e];
#pragma unroll
    for (int j = 0; j < DCONV; j++) {
        int tt = t - (DCONV - 1) + j;
        if (tt >= 0) acc = fmaf(xz[(size_t)tt * (2 * ED) + e], wr[j], acc);
    }
    float v = acc / (1.f + __expf(-acc));
    xb[i] = v;
    __nv_bfloat16 h = __float2bfloat16(v);
    oh[i] = h;
    ol[i] = __float2bfloat16(v - __bfloat162float(h));
}

// ---------------- bf16 3-term split GEMM ----------------
// EPI: 0 = store, 1 = softplus(acc + aux[n]), 2 = C += acc, 3 = atomicAdd (split-K).
// strideK = row stride of A/B in elements; gridDim.z slices K (offset z*K).
#define ROWB 80

template<int MT, int EPI>
__global__ __launch_bounds__(256, 2) void hgemm_k(
    const __nv_bfloat16* __restrict__ Ah, const __nv_bfloat16* __restrict__ Al,
    const __nv_bfloat16* __restrict__ Bh, const __nv_bfloat16* __restrict__ Bl,
    float* __restrict__ C, int K, int strideK, int ldc, int Nlim,
    const float* __restrict__ aux)
{
    constexpr int ASZ   = MT * 32 * ROWB;
    constexpr int BSZ   = 128 * ROWB;
    constexpr int BUFSZ = 2 * ASZ + 2 * BSZ;

    extern __shared__ char dynsm[];
    uint32_t base = smem_u32(dynsm);

    int tid = threadIdx.x, lane = tid & 31, wid = tid >> 5;
    int m0 = blockIdx.x * (MT * 32), n0 = blockIdx.y * 128;
    int wm = (wid & 1) * (MT * 16), wn = (wid >> 1) * 32;
    int koff = blockIdx.z * K;

    int lr = tid >> 2;
    int lk = (tid & 3) * 8;

    const __nv_bfloat16* gAh0 = Ah + (size_t)(m0 + lr) * strideK + koff + lk;
    const __nv_bfloat16* gAl0 = Al + (size_t)(m0 + lr) * strideK + koff + lk;
    const __nv_bfloat16* gAh1 = (MT == 4) ? gAh0 + (size_t)64 * strideK : gAh0;
    const __nv_bfloat16* gAl1 = (MT == 4) ? gAl0 + (size_t)64 * strideK : gAl0;
    const __nv_bfloat16* gBh0 = Bh + (size_t)(n0 + lr) * strideK + koff + lk;
    const __nv_bfloat16* gBl0 = Bl + (size_t)(n0 + lr) * strideK + koff + lk;
    const __nv_bfloat16* gBh1 = gBh0 + (size_t)64 * strideK;
    const __nv_bfloat16* gBl1 = gBl0 + (size_t)64 * strideK;

    uint32_t st0 = (uint32_t)(lr * ROWB + lk * 2);
    uint32_t st1 = st0 + 64 * ROWB;

    uint32_t aOff = (uint32_t)((wm + (lane & 15)) * ROWB + (lane >> 4) * 16);
    uint32_t bOff4 = (uint32_t)((wn + ((lane >> 4) << 3) + (lane & 7)) * ROWB
                                + ((lane >> 3) & 1) * 16);

    float acc[MT][4][4];
#pragma unroll
    for (int i = 0; i < MT; i++)
#pragma unroll
        for (int j = 0; j < 4; j++)
#pragma unroll
            for (int r = 0; r < 4; r++) acc[i][j][r] = 0.f;

    int nchunk = K >> 5;

    auto prefetch = [&](int kc, int buf) {
        int ko = kc * 32;
        uint32_t bo = base + buf * BUFSZ;
        if (MT == 4) {
            cpa16(bo + st0, gAh0 + ko);        cpa16(bo + st1, gAh1 + ko);
            cpa16(bo + ASZ + st0, gAl0 + ko);  cpa16(bo + ASZ + st1, gAl1 + ko);
        } else if (MT == 2) {
            cpa16(bo + st0, gAh0 + ko);
            cpa16(bo + ASZ + st0, gAl0 + ko);
        } else {
            if (lr < 32) {
                cpa16(bo + st0, gAh0 + ko);
                cpa16(bo + ASZ + st0, gAl0 + ko);
            }
        }
        cpa16(bo + 2 * ASZ + st0, gBh0 + ko);        cpa16(bo + 2 * ASZ + st1, gBh1 + ko);
        cpa16(bo + 2 * ASZ + BSZ + st0, gBl0 + ko);  cpa16(bo + 2 * ASZ + BSZ + st1, gBl1 + ko);
    };

    prefetch(0, 0);
    CP_COMMIT();

    for (int kc = 0; kc < nchunk; kc++) {
        CP_WAIT0();
        __syncthreads();
        if (kc + 1 < nchunk) prefetch(kc + 1, (kc + 1) & 1);
        CP_COMMIT();

        uint32_t bo = base + (kc & 1) * BUFSZ;
#pragma unroll
        for (int kk = 0; kk < 2; kk++) {
            uint32_t kb = kk * 32;
            uint32_t bh4[2][4], bl4[2][4];
#pragma unroll
            for (int p = 0; p < 2; p++) {
                uint32_t off = bOff4 + p * 16 * ROWB + kb;
                ldsm4(bh4[p], bo + 2 * ASZ + off);
                ldsm4(bl4[p], bo + 2 * ASZ + BSZ + off);
            }
#pragma unroll
            for (int mt = 0; mt < MT; mt++) {
                uint32_t ah[4];
                ldsm4(ah, bo + aOff + mt * 16 * ROWB + kb);
#pragma unroll
                for (int nt = 0; nt < 4; nt++)
                    mma_bf16(acc[mt][nt], ah, &bh4[nt >> 1][(nt & 1) * 2]);
#pragma unroll
                for (int nt = 0; nt < 4; nt++)
                    mma_bf16(acc[mt][nt], ah, &bl4[nt >> 1][(nt & 1) * 2]);
            }
#pragma unroll
            for (int mt = 0; mt < MT; mt++) {
                uint32_t al[4];
                ldsm4(al, bo + ASZ + aOff + mt * 16 * ROWB + kb);
#pragma unroll
                for (int nt = 0; nt < 4; nt++)
                    mma_bf16(acc[mt][nt], al, &bh4[nt >> 1][(nt & 1) * 2]);
            }
        }
    }

    int er = m0 + wm + (lane >> 2);
    int ec = n0 + wn + (lane & 3) * 2;
#pragma unroll
    for (int mt = 0; mt < MT; mt++) {
#pragma unroll
        for (int nt = 0; nt < 4; nt++) {
            int col = ec + nt * 8;
            if (col >= Nlim) continue;
            float* p0 = C + (size_t)(er + mt * 16) * ldc + col;
            float* p1 = p0 + 8 * ldc;
            float d0 = acc[mt][nt][0], d1 = acc[mt][nt][1];
            float d2 = acc[mt][nt][2], d3 = acc[mt][nt][3];
            if (EPI == 3) {
                atomicAdd(p0, d0); atomicAdd(p0 + 1, d1);
                atomicAdd(p1, d2); atomicAdd(p1 + 1, d3);
                continue;
            }
            if (EPI == 1) {
                float b0 = aux[col], b1 = aux[col + 1];
                d0 += b0; d1 += b1; d2 += b0; d3 += b1;
                d0 = (d0 > 20.f) ? d0 : log1pf(__expf(d0));
                d1 = (d1 > 20.f) ? d1 : log1pf(__expf(d1));
                d2 = (d2 > 20.f) ? d2 : log1pf(__expf(d2));
                d3 = (d3 > 20.f) ? d3 : log1pf(__expf(d3));
            } else if (EPI == 2) {
                float2 o0 = *(float2*)p0, o1 = *(float2*)p1;
                d0 += o0.x; d1 += o0.y; d2 += o1.x; d3 += o1.y;
            }
            *(float2*)p0 = make_float2(d0, d1);
            *(float2*)p1 = make_float2(d2, d3);
        }
    }
}

// ---------------- int8 2-digit GEMM (lm_head): 128x128 tile, 256 thr ----------------
// C[m,n] = sA[m]*sB[n]/16129 * (A1B1 + (A1B2 + A2B1)/128)
__global__ __launch_bounds__(256, 1) void igemm_k(
    const int8_t* __restrict__ A1, const int8_t* __restrict__ A2,
    const int8_t* __restrict__ B1, const int8_t* __restrict__ B2,
    const float* __restrict__ sA, const float* __restrict__ sB,
    float* __restrict__ C, int K, int ldc)
{
    constexpr int ASZ   = 128 * ROWB;        // 10240 bytes per array
    constexpr int BUFSZ = 4 * ASZ;

    extern __shared__ char dynsm[];
    uint32_t base = smem_u32(dynsm);

    int tid = threadIdx.x, lane = tid & 31, wid = tid >> 5;
    int m0 = blockIdx.x * 128, n0 = blockIdx.y * 128;
    int wm = (wid & 1) * 64, wn = (wid >> 1) * 32;

    int lr = tid >> 2;            // 0..63
    int lk = (tid & 3) * 16;      // byte offset within 64B chunk

    const int8_t* gA1 = A1 + (size_t)(m0 + lr) * K + lk;
    const int8_t* gA2 = A2 + (size_t)(m0 + lr) * K + lk;
    const int8_t* gB1 = B1 + (size_t)(n0 + lr) * K + lk;
    const int8_t* gB2 = B2 + (size_t)(n0 + lr) * K + lk;
    const size_t rstep = (size_t)64 * K;

    uint32_t st0 = (uint32_t)(lr * ROWB + lk);
    uint32_t st1 = st0 + 64 * ROWB;

    uint32_t aOff = (uint32_t)((wm + (lane & 15)) * ROWB + (lane >> 4) * 16);
    uint32_t bOff4 = (uint32_t)((wn + ((lane >> 4) << 3) + (lane & 7)) * ROWB
                                + ((lane >> 3) & 1) * 16);

    int acc1[4][4][4], accX[4][4][4];
#pragma unroll
    for (int i = 0; i < 4; i++)
#pragma unroll
        for (int j = 0; j < 4; j++)
#pragma unroll
            for (int r = 0; r < 4; r++) { acc1[i][j][r] = 0; accX[i][j][r] = 0; }

    int nchunk = K >> 6;   // 64 int8 per chunk

    auto prefetch = [&](int kc, int buf) {
        int ko = kc * 64;
        uint32_t bo = base + buf * BUFSZ;
        cpa16(bo + st0,           gA1 + ko);  cpa16(bo + st1,           gA1 + rstep + ko);
        cpa16(bo + ASZ + st0,     gA2 + ko);  cpa16(bo + ASZ + st1,     gA2 + rstep + ko);
        cpa16(bo + 2 * ASZ + st0, gB1 + ko);  cpa16(bo + 2 * ASZ + st1, gB1 + rstep + ko);
        cpa16(bo + 3 * ASZ + st0, gB2 + ko);  cpa16(bo + 3 * ASZ + st1, gB2 + rstep + ko);
    };

    prefetch(0, 0);
    CP_COMMIT();

    for (int kc = 0; kc < nchunk; kc++) {
        CP_WAIT0();
        __syncthreads();
        if (kc + 1 < nchunk) prefetch(kc + 1, (kc + 1) & 1);
        CP_COMMIT();

        uint32_t bo = base + (kc & 1) * BUFSZ;
#pragma unroll
        for (int kk = 0; kk < 2; kk++) {
            uint32_t kb = kk * 32;   // 32 bytes = one k32 step
            uint32_t b1f[2][4], b2f[2][4];
#pragma unroll
            for (int p = 0; p < 2; p++) {
                uint32_t off = bOff4 + p * 16 * ROWB + kb;
                ldsm4(b1f[p], bo + 2 * ASZ + off);
                ldsm4(b2f[p], bo + 3 * ASZ + off);
            }
#pragma unroll
            for (int mt = 0; mt < 4; mt++) {
                uint32_t a1[4];
                ldsm4(a1, bo + aOff + mt * 16 * ROWB + kb);
#pragma unroll
                for (int nt = 0; nt < 4; nt++)
                    mma_s8(acc1[mt][nt], a1, &b1f[nt >> 1][(nt & 1) * 2]);
#pragma unroll
                for (int nt = 0; nt < 4; nt++)
                    mma_s8(accX[mt][nt], a1, &b2f[nt >> 1][(nt & 1) * 2]);
            }
#pragma unroll
            for (int mt = 0; mt < 4; mt++) {
                uint32_t a2[4];
                ldsm4(a2, bo + ASZ + aOff + mt * 16 * ROWB + kb);
#pragma unroll
                for (int nt = 0; nt < 4; nt++)
                    mma_s8(accX[mt][nt], a2, &b1f[nt >> 1][(nt & 1) * 2]);
            }
        }
    }

    int er = m0 + wm + (lane >> 2);
    int ec = n0 + wn + (lane & 3) * 2;
    const float inv127sq = 1.f / 16129.f;
#pragma unroll
    for (int mt = 0; mt < 4; mt++) {
        float sa0 = sA[er + mt * 16] * inv127sq;
        float sa1 = sA[er + mt * 16 + 8] * inv127sq;
#pragma unroll
        for (int nt = 0; nt < 4; nt++) {
            int col = ec + nt * 8;
            float sb0 = sB[col], sb1 = sB[col + 1];
            float v0 = (float)acc1[mt][nt][0] + (float)accX[mt][nt][0] * 0.0078125f;
            float v1 = (float)acc1[mt][nt][1] + (float)accX[mt][nt][1] * 0.0078125f;
            float v2 = (float)acc1[mt][nt][2] + (float)accX[mt][nt][2] * 0.0078125f;
            float v3 = (float)acc1[mt][nt][3] + (float)accX[mt][nt][3] * 0.0078125f;
            float* p0 = C + (size_t)(er + mt * 16) * ldc + col;
            float* p1 = p0 + 8 * ldc;
            *(float2*)p0 = make_float2(v0 * sa0 * sb0, v1 * sa0 * sb1);
            *(float2*)p1 = make_float2(v2 * sa1 * sb0, v3 * sa1 * sb1);
        }
    }
}

// ---------------- selective scan ----------------
__global__ void scan1_k(const float* __restrict__ delta, const float* __restrict__ xb,
                        const float* __restrict__ dbc, const float* __restrict__ A_log,
                        float* __restrict__ cp, float* __restrict__ cs) {
    int i = blockIdx.x * blockDim.x + threadIdx.x;
    if (i >= NCHUNK * ED) return;
    int c = i / ED, e = i % ED;
    float A[NST], h[NST], p[NST];
#pragma unroll
    for (int n = 0; n < NST; n++) {
        A[n] = -__expf(A_log[e * NST + n]);
        h[n] = 0.f; p[n] = 1.f;
    }
    int t0 = c * CHUNK;
    for (int t = t0; t < t0 + CHUNK; t++) {
        float d  = delta[(size_t)t * ED + e];
        float xv = xb[(size_t)t * ED + e];
        float dx = d * xv;
        const float* Bt = dbc + (size_t)t * DXP + DTR;
#pragma unroll
        for (int n = 0; n < NST; n++) {
            float a = __expf(d * A[n]);
            p[n] *= a;
            h[n] = fmaf(a, h[n], dx * Bt[n]);
        }
    }
    size_t o = (size_t)i * NST;
#pragma unroll
    for (int n = 0; n < NST; n++) { cp[o + n] = p[n]; cs[o + n] = h[n]; }
}

__global__ void carry_k(const float* __restrict__ cp, const float* __restrict__ cs,
                        float* __restrict__ cc) {
    int i = blockIdx.x * blockDim.x + threadIdx.x;
    if (i >= ED * NST) return;
    float H = 0.f;
    for (int c = 0; c < NCHUNK; c++) {
        size_t idx = (size_t)c * ED * NST + i;
        cc[idx] = H;
        H = fmaf(cp[idx], H, cs[idx]);
    }
}

__global__ void scan2_k(const float* __restrict__ delta, const float* __restrict__ xb,
                        const float* __restrict__ dbc, const float* __restrict__ A_log,
                        const float* __restrict__ cc, const float* __restrict__ Dp,
                        const float* __restrict__ xz,
                        __nv_bfloat16* __restrict__ yzh, __nv_bfloat16* __restrict__ yzl) {
    int i = blockIdx.x * blockDim.x + threadIdx.x;
    if (i >= NCHUNK * ED) return;
    int c = i / ED, e = i % ED;
    float A[NST], h[NST];
#pragma unroll
    for (int n = 0; n < NST; n++) {
        A[n] = -__expf(A_log[e * NST + n]);
        h[n] = cc[(size_t)i * NST + n];
    }
    float Dv = Dp[e];
    int t0 = c * CHUNK;
    for (int t = t0; t < t0 + CHUNK; t++) {
        float d  = delta[(size_t)t * ED + e];
        float xv = xb[(size_t)t * ED + e];
        float dx = d * xv;
        const float* Bt = dbc + (size_t)t * DXP + DTR;
        const float* Ct = dbc + (size_t)t * DXP + DTR + NST;
        float y = 0.f;
#pragma unroll
        for (int n = 0; n < NST; n++) {
            float a = __expf(d * A[n]);
            h[n] = fmaf(a, h[n], dx * Bt[n]);
            y = fmaf(h[n], Ct[n], y);
        }
        float zv = xz[(size_t)t * (2 * ED) + ED + e];
        float sz = zv / (1.f + __expf(-zv));
        float v = (y + xv * Dv) * sz;
        __nv_bfloat16 hb = __float2bfloat16(v);
        yzh[(size_t)t * ED + e] = hb;
        yzl[(size_t)t * ED + e] = __float2bfloat16(v - __bfloat162float(hb));
    }
}

// ---------------- host orchestration ----------------
extern "C" void kernel_launch(void* const* d_in, const int* in_sizes, int n_in,
                              void* d_out, int out_size) {
    const int*   tokens  = (const int*)d_in[0];
    const float* emb     = (const float*)d_in[1];
    const float* norm_w  = (const float*)d_in[2];
    const float* in_proj = (const float*)d_in[3];
    const float* conv_w  = (const float*)d_in[4];
    const float* conv_b  = (const float*)d_in[5];
    const float* x_proj  = (const float*)d_in[6];
    const float* dt_w    = (const float*)d_in[7];
    const float* dt_b    = (const float*)d_in[8];
    const float* A_log   = (const float*)d_in[9];
    const float* Dp      = (const float*)d_in[10];
    const float* out_prj = (const float*)d_in[11];
    const float* norm_f  = (const float*)d_in[12];
    const float* lm_head = (const float*)d_in[13];
    float* logits = (float*)d_out;

    float *x, *xz, *xb, *dbc, *delta, *cp, *cs, *cc, *sa, *sb;
    __nv_bfloat16 *ah, *al, *dh, *dl, *wh, *wl;
    int8_t *qa1, *qa2, *qb1, *qb2;
    cudaGetSymbolAddress((void**)&x,     g_x);
    cudaGetSymbolAddress((void**)&xz,    g_xz);
    cudaGetSymbolAddress((void**)&xb,    g_xb);
    cudaGetSymbolAddress((void**)&dbc,   g_dbc);
    cudaGetSymbolAddress((void**)&delta, g_delta);
    cudaGetSymbolAddress((void**)&cp,    g_cp);
    cudaGetSymbolAddress((void**)&cs,    g_cs);
    cudaGetSymbolAddress((void**)&cc,    g_cc);
    cudaGetSymbolAddress((void**)&ah,    g_ah);
    cudaGetSymbolAddress((void**)&al,    g_al);
    cudaGetSymbolAddress((void**)&dh,    g_dh);
    cudaGetSymbolAddress((void**)&dl,    g_dl);
    cudaGetSymbolAddress((void**)&wh,    g_wh);
    cudaGetSymbolAddress((void**)&wl,    g_wl);
    cudaGetSymbolAddress((void**)&qa1,   g_qa1);
    cudaGetSymbolAddress((void**)&qa2,   g_qa2);
    cudaGetSymbolAddress((void**)&qb1,   g_qb1);
    cudaGetSymbolAddress((void**)&qb2,   g_qb2);
    cudaGetSymbolAddress((void**)&sa,    g_sa);
    cudaGetSymbolAddress((void**)&sb,    g_sb);

    const int SM4 = 2 * (2 * 4 * 32 * ROWB + 2 * 128 * ROWB);   // 81920
    const int SM2 = 2 * (2 * 2 * 32 * ROWB + 2 * 128 * ROWB);   // 61440
    const int SM1 = 2 * (2 * 1 * 32 * ROWB + 2 * 128 * ROWB);   // 51200
    const int SMI = 2 * 4 * 128 * ROWB;                          // 81920
    static bool attr_done = false;
    if (!attr_done) {
        cudaFuncSetAttribute(hgemm_k<2,0>, cudaFuncAttributeMaxDynamicSharedMemorySize, SM2);
        cudaFuncSetAttribute(hgemm_k<2,2>, cudaFuncAttributeMaxDynamicSharedMemorySize, SM2);
        cudaFuncSetAttribute(hgemm_k<1,3>, cudaFuncAttributeMaxDynamicSharedMemorySize, SM1);
        cudaFuncSetAttribute(hgemm_k<4,1>, cudaFuncAttributeMaxDynamicSharedMemorySize, SM4);
        cudaFuncSetAttribute(igemm_k,      cudaFuncAttributeMaxDynamicSharedMemorySize, SMI);
        attr_done = true;
    }

    embed_k<<<(L * D + 255) / 256, 256>>>(tokens, emb, x);

    for (int l = 0; l < NL; l++) {
        rmsnorm_split_k<<<L, 256>>>(x, norm_w + l * D, ah, al);

        // xz = xn @ in_proj^T
        int nwi = 2 * ED * D;
        split4_k<<<(nwi / 4 + 255) / 256, 256>>>(
            (const float4*)(in_proj + (size_t)l * nwi), (__nv_bfloat162*)wh, (__nv_bfloat162*)wl, nwi / 4);
        hgemm_k<2,0><<<dim3(L / 64, 2 * ED / 128), 256, SM2>>>(
            ah, al, wh, wl, xz, D, D, 2 * ED, 2 * ED, nullptr);

        // conv + silu (also emits bf16 hi/lo of xb into ah/al)
        conv_silu_split_k<<<(L * ED + 255) / 256, 256>>>(
            xz, conv_w + (size_t)l * ED * DCONV, conv_b + l * ED, xb, ah, al);

        // dbc = xb @ x_proj^T  (N=80 padded to 128, split-K=2 with atomics)
        split_pad_k<<<(128 * ED + 255) / 256, 256>>>(
            x_proj + (size_t)l * DXP * ED, wh, wl, 128, ED, DXP, ED, ED);
        cudaMemsetAsync(dbc, 0, (size_t)L * DXP * sizeof(float));
        hgemm_k<1,3><<<dim3(L / 32, 1, 2), 256, SM1>>>(
            ah, al, wh, wl, dbc, ED / 2, ED, DXP, DXP, nullptr);

        // delta = softplus(dbc[:, :48] @ dt_w^T + dt_b)   (K=48 padded to 64)
        split_pad_k<<<(L * 64 + 255) / 256, 256>>>(dbc, dh, dl, L, 64, L, DTR, DXP);
        split_pad_k<<<(ED * 64 + 255) / 256, 256>>>(
            dt_w + (size_t)l * ED * DTR, wh, wl, ED, 64, ED, DTR, DTR);
        hgemm_k<4,1><<<dim3(L / 128, ED / 128), 256, SM4>>>(
            dh, dl, wh, wl, delta, 64, 64, ED, ED, dt_b + l * ED);

        // selective scan (writes gated output as bf16 hi/lo into ah/al)
        scan1_k<<<(NCHUNK * ED) / 256, 256>>>(delta, xb, dbc,
                                              A_log + (size_t)l * ED * NST, cp, cs);
        carry_k<<<(ED * NST) / 256, 256>>>(cp, cs, cc);
        scan2_k<<<(NCHUNK * ED) / 256, 256>>>(delta, xb, dbc,
                                              A_log + (size_t)l * ED * NST, cc,
                                              Dp + l * ED, xz, ah, al);

        // x += yz @ out_proj^T
        int nwo = D * ED;
        split4_k<<<(nwo / 4 + 255) / 256, 256>>>(
            (const float4*)(out_prj + (size_t)l * nwo), (__nv_bfloat162*)wh, (__nv_bfloat162*)wl, nwo / 4);
        hgemm_k<2,2><<<dim3(L / 64, D / 128), 256, SM2>>>(
            ah, al, wh, wl, x, ED, ED, D, D, nullptr);
    }

    // final norm -> int8 digits of activations; quantize lm_head; int8 GEMM
    rmsnorm_quant_k<<<L, 256>>>(x, norm_f, qa1, qa2, sa);
    quant_rows_k<<<VOCAB, 128>>>(lm_head, D, qb1, qb2, sb);
    igemm_k<<<dim3(L / 128, VOCAB / 128), 256, SMI>>>(
        qa1, qa2, qb1, qb2, sa, sb, logits, D, VOCAB);
}

// round 9
// speedup vs baseline: 1.8341x; 1.8341x over previous
#include <cuda_runtime.h>
#include <cuda_bf16.h>
#include <cuda_fp16.h>
#include <math.h>
#include <cstdint>

// ---------------- problem constants ----------------
#define L       2048
#define D       768
#define ED      1536
#define NL      4
#define NST     16
#define DTR     48
#define DXP     80
#define VOCAB   32000
#define DCONV   4
#define CHUNK   64
#define NCHUNK  (L / CHUNK)

// ---------------- scratch ----------------
__device__ __align__(256) float g_x    [L * D];
__device__ __align__(256) float g_xz   [L * 2 * ED];
__device__ __align__(256) float g_xb   [L * ED];
__device__ __align__(256) float g_dbc  [L * DXP];
__device__ __align__(256) float g_delta[L * ED];
__device__ __align__(256) float g_cp   [NCHUNK * ED * NST];
__device__ __align__(256) float g_cs   [NCHUNK * ED * NST];
__device__ __align__(256) float g_cc   [NCHUNK * ED * NST];
__device__ __align__(256) __nv_bfloat16 g_ah[L * ED];
__device__ __align__(256) __nv_bfloat16 g_al[L * ED];
__device__ __align__(256) __nv_bfloat16 g_dh[L * 64];
__device__ __align__(256) __nv_bfloat16 g_dl[L * 64];
__device__ __align__(256) __nv_bfloat16 g_wh[VOCAB * D];   // also fp16 lm_head weights
__device__ __align__(256) __nv_bfloat16 g_wl[2 * ED * D];

// ---------------- helpers ----------------
__device__ __forceinline__ uint32_t smem_u32(const void* p) {
    uint32_t a;
    asm("{ .reg .u64 t; cvta.to.shared.u64 t, %1; cvt.u32.u64 %0, t; }" : "=r"(a) : "l"(p));
    return a;
}
__device__ __forceinline__ void ldsm4(uint32_t* r, uint32_t addr) {
    asm volatile("ldmatrix.sync.aligned.m8n8.x4.shared.b16 {%0,%1,%2,%3}, [%4];"
                 : "=r"(r[0]), "=r"(r[1]), "=r"(r[2]), "=r"(r[3]) : "r"(addr));
}
__device__ __forceinline__ void mma_bf16(float* d, const uint32_t* a, const uint32_t* b) {
    asm volatile(
        "mma.sync.aligned.m16n8k16.row.col.f32.bf16.bf16.f32 "
        "{%0,%1,%2,%3}, {%4,%5,%6,%7}, {%8,%9}, {%0,%1,%2,%3};"
        : "+f"(d[0]), "+f"(d[1]), "+f"(d[2]), "+f"(d[3])
        : "r"(a[0]), "r"(a[1]), "r"(a[2]), "r"(a[3]), "r"(b[0]), "r"(b[1]));
}
__device__ __forceinline__ void mma_f16(float* d, const uint32_t* a, const uint32_t* b) {
    asm volatile(
        "mma.sync.aligned.m16n8k16.row.col.f32.f16.f16.f32 "
        "{%0,%1,%2,%3}, {%4,%5,%6,%7}, {%8,%9}, {%0,%1,%2,%3};"
        : "+f"(d[0]), "+f"(d[1]), "+f"(d[2]), "+f"(d[3])
        : "r"(a[0]), "r"(a[1]), "r"(a[2]), "r"(a[3]), "r"(b[0]), "r"(b[1]));
}
__device__ __forceinline__ void cpa16(uint32_t d, const void* s) {
    asm volatile("cp.async.cg.shared.global [%0], [%1], 16;" :: "r"(d), "l"(s));
}
#define CP_COMMIT() asm volatile("cp.async.commit_group;" ::: "memory")
#define CP_WAIT0()  asm volatile("cp.async.wait_group 0;" ::: "memory")

// ---------------- embedding ----------------
__global__ void embed_k(const int* __restrict__ tok, const float* __restrict__ emb,
                        float* __restrict__ x) {
    int i = blockIdx.x * blockDim.x + threadIdx.x;
    if (i >= L * D) return;
    int t = i / D, d = i % D;
    x[i] = emb[(size_t)tok[t] * D + d];
}

// ---------------- fp32 -> bf16 hi/lo split ----------------
__global__ void split4_k(const float4* __restrict__ src, __nv_bfloat162* __restrict__ hi,
                         __nv_bfloat162* __restrict__ lo, int n4) {
    int i = blockIdx.x * blockDim.x + threadIdx.x;
    if (i >= n4) return;
    float4 v = src[i];
    __nv_bfloat16 hx = __float2bfloat16(v.x), hy = __float2bfloat16(v.y);
    __nv_bfloat16 hz = __float2bfloat16(v.z), hw = __float2bfloat16(v.w);
    hi[2 * i]     = __nv_bfloat162(hx, hy);
    hi[2 * i + 1] = __nv_bfloat162(hz, hw);
    lo[2 * i]     = __nv_bfloat162(__float2bfloat16(v.x - __bfloat162float(hx)),
                                   __float2bfloat16(v.y - __bfloat162float(hy)));
    lo[2 * i + 1] = __nv_bfloat162(__float2bfloat16(v.z - __bfloat162float(hz)),
                                   __float2bfloat16(v.w - __bfloat162float(hw)));
}

// padded split
__global__ void split_pad_k(const float* __restrict__ src, __nv_bfloat16* __restrict__ hi,
                            __nv_bfloat16* __restrict__ lo,
                            int Mdst, int Kp, int Msrc, int Kin, int Ssrc) {
    int i = blockIdx.x * blockDim.x + threadIdx.x;
    if (i >= Mdst * Kp) return;
    int r = i / Kp, c = i % Kp;
    float v = (r < Msrc && c < Kin) ? src[(size_t)r * Ssrc + c] : 0.f;
    __nv_bfloat16 h = __float2bfloat16(v);
    hi[i] = h;
    lo[i] = __float2bfloat16(v - __bfloat162float(h));
}

// fp32 -> fp16 convert (weights for lm_head)
__global__ void tofp16_k(const float4* __restrict__ src, __half2* __restrict__ dst, int n4) {
    int i = blockIdx.x * blockDim.x + threadIdx.x;
    if (i >= n4) return;
    float4 v = src[i];
    dst[2 * i]     = __floats2half2_rn(v.x, v.y);
    dst[2 * i + 1] = __floats2half2_rn(v.z, v.w);
}

// ---------------- RMSNorm -> bf16 hi/lo ----------------
__global__ void rmsnorm_split_k(const float* __restrict__ x, const float* __restrict__ w,
                                __nv_bfloat16* __restrict__ oh, __nv_bfloat16* __restrict__ ol) {
    int t = blockIdx.x;
    const float* xr = x + (size_t)t * D;
    float s = 0.f;
    for (int d = threadIdx.x; d < D; d += 256) { float v = xr[d]; s += v * v; }
    __shared__ float red[256];
    red[threadIdx.x] = s;
    __syncthreads();
    for (int o = 128; o > 0; o >>= 1) {
        if (threadIdx.x < o) red[threadIdx.x] += red[threadIdx.x + o];
        __syncthreads();
    }
    float inv = rsqrtf(red[0] / (float)D + 1e-5f);
    for (int d = threadIdx.x; d < D; d += 256) {
        float v = xr[d] * inv * w[d];
        __nv_bfloat16 h = __float2bfloat16(v);
        oh[(size_t)t * D + d] = h;
        ol[(size_t)t * D + d] = __float2bfloat16(v - __bfloat162float(h));
    }
}

// ---------------- RMSNorm -> fp16 hi/lo (for lm_head A) ----------------
__global__ void rmsnorm_splith_k(const float* __restrict__ x, const float* __restrict__ w,
                                 __half* __restrict__ oh, __half* __restrict__ ol) {
    int t = blockIdx.x;
    const float* xr = x + (size_t)t * D;
    float s = 0.f;
    for (int d = threadIdx.x; d < D; d += 256) { float v = xr[d]; s += v * v; }
    __shared__ float red[256];
    red[threadIdx.x] = s;
    __syncthreads();
    for (int o = 128; o > 0; o >>= 1) {
        if (threadIdx.x < o) red[threadIdx.x] += red[threadIdx.x + o];
        __syncthreads();
    }
    float inv = rsqrtf(red[0] / (float)D + 1e-5f);
    for (int d = threadIdx.x; d < D; d += 256) {
        float v = xr[d] * inv * w[d];
        __half h = __float2half_rn(v);
        oh[(size_t)t * D + d] = h;
        ol[(size_t)t * D + d] = __float2half_rn(v - __half2float(h));
    }
}

// ---------------- conv1d + silu, fused bf16 hi/lo split of output ----------------
__global__ void conv_silu_split_k(const float* __restrict__ xz, const float* __restrict__ w,
                                  const float* __restrict__ b, float* __restrict__ xb,
                                  __nv_bfloat16* __restrict__ oh, __nv_bfloat16* __restrict__ ol) {
    int i = blockIdx.x * blockDim.x + threadIdx.x;
    if (i >= L * ED) return;
    int t = i / ED, e = i % ED;
    const float* wr = w + e * DCONV;
    float acc = b[e];
#pragma unroll
    for (int j = 0; j < DCONV; j++) {
        int tt = t - (DCONV - 1) + j;
        if (tt >= 0) acc = fmaf(xz[(size_t)tt * (2 * ED) + e], wr[j], acc);
    }
    float v = acc / (1.f + __expf(-acc));
    xb[i] = v;
    __nv_bfloat16 h = __float2bfloat16(v);
    oh[i] = h;
    ol[i] = __float2bfloat16(v - __bfloat162float(h));
}

// ---------------- bf16 3-term split GEMM ----------------
// EPI: 0 = store, 1 = softplus(acc + aux[n]), 2 = C += acc, 3 = atomicAdd (split-K).
#define ROWB 80

template<int MT, int EPI>
__global__ __launch_bounds__(256, 2) void hgemm_k(
    const __nv_bfloat16* __restrict__ Ah, const __nv_bfloat16* __restrict__ Al,
    const __nv_bfloat16* __restrict__ Bh, const __nv_bfloat16* __restrict__ Bl,
    float* __restrict__ C, int K, int strideK, int ldc, int Nlim,
    const float* __restrict__ aux)
{
    constexpr int ASZ   = MT * 32 * ROWB;
    constexpr int BSZ   = 128 * ROWB;
    constexpr int BUFSZ = 2 * ASZ + 2 * BSZ;

    extern __shared__ char dynsm[];
    uint32_t base = smem_u32(dynsm);

    int tid = threadIdx.x, lane = tid & 31, wid = tid >> 5;
    int m0 = blockIdx.x * (MT * 32), n0 = blockIdx.y * 128;
    int wm = (wid & 1) * (MT * 16), wn = (wid >> 1) * 32;
    int koff = blockIdx.z * K;

    int lr = tid >> 2;
    int lk = (tid & 3) * 8;

    const __nv_bfloat16* gAh0 = Ah + (size_t)(m0 + lr) * strideK + koff + lk;
    const __nv_bfloat16* gAl0 = Al + (size_t)(m0 + lr) * strideK + koff + lk;
    const __nv_bfloat16* gAh1 = (MT == 4) ? gAh0 + (size_t)64 * strideK : gAh0;
    const __nv_bfloat16* gAl1 = (MT == 4) ? gAl0 + (size_t)64 * strideK : gAl0;
    const __nv_bfloat16* gBh0 = Bh + (size_t)(n0 + lr) * strideK + koff + lk;
    const __nv_bfloat16* gBl0 = Bl + (size_t)(n0 + lr) * strideK + koff + lk;
    const __nv_bfloat16* gBh1 = gBh0 + (size_t)64 * strideK;
    const __nv_bfloat16* gBl1 = gBl0 + (size_t)64 * strideK;

    uint32_t st0 = (uint32_t)(lr * ROWB + lk * 2);
    uint32_t st1 = st0 + 64 * ROWB;

    uint32_t aOff = (uint32_t)((wm + (lane & 15)) * ROWB + (lane >> 4) * 16);
    uint32_t bOff4 = (uint32_t)((wn + ((lane >> 4) << 3) + (lane & 7)) * ROWB
                                + ((lane >> 3) & 1) * 16);

    float acc[MT][4][4];
#pragma unroll
    for (int i = 0; i < MT; i++)
#pragma unroll
        for (int j = 0; j < 4; j++)
#pragma unroll
            for (int r = 0; r < 4; r++) acc[i][j][r] = 0.f;

    int nchunk = K >> 5;

    auto prefetch = [&](int kc, int buf) {
        int ko = kc * 32;
        uint32_t bo = base + buf * BUFSZ;
        if (MT == 4) {
            cpa16(bo + st0, gAh0 + ko);        cpa16(bo + st1, gAh1 + ko);
            cpa16(bo + ASZ + st0, gAl0 + ko);  cpa16(bo + ASZ + st1, gAl1 + ko);
        } else if (MT == 2) {
            cpa16(bo + st0, gAh0 + ko);
            cpa16(bo + ASZ + st0, gAl0 + ko);
        } else {
            if (lr < 32) {
                cpa16(bo + st0, gAh0 + ko);
                cpa16(bo + ASZ + st0, gAl0 + ko);
            }
        }
        cpa16(bo + 2 * ASZ + st0, gBh0 + ko);        cpa16(bo + 2 * ASZ + st1, gBh1 + ko);
        cpa16(bo + 2 * ASZ + BSZ + st0, gBl0 + ko);  cpa16(bo + 2 * ASZ + BSZ + st1, gBl1 + ko);
    };

    prefetch(0, 0);
    CP_COMMIT();

    for (int kc = 0; kc < nchunk; kc++) {
        CP_WAIT0();
        __syncthreads();
        if (kc + 1 < nchunk) prefetch(kc + 1, (kc + 1) & 1);
        CP_COMMIT();

        uint32_t bo = base + (kc & 1) * BUFSZ;
#pragma unroll
        for (int kk = 0; kk < 2; kk++) {
            uint32_t kb = kk * 32;
            uint32_t bh4[2][4], bl4[2][4];
#pragma unroll
            for (int p = 0; p < 2; p++) {
                uint32_t off = bOff4 + p * 16 * ROWB + kb;
                ldsm4(bh4[p], bo + 2 * ASZ + off);
                ldsm4(bl4[p], bo + 2 * ASZ + BSZ + off);
            }
#pragma unroll
            for (int mt = 0; mt < MT; mt++) {
                uint32_t ah[4];
                ldsm4(ah, bo + aOff + mt * 16 * ROWB + kb);
#pragma unroll
                for (int nt = 0; nt < 4; nt++)
                    mma_bf16(acc[mt][nt], ah, &bh4[nt >> 1][(nt & 1) * 2]);
#pragma unroll
                for (int nt = 0; nt < 4; nt++)
                    mma_bf16(acc[mt][nt], ah, &bl4[nt >> 1][(nt & 1) * 2]);
            }
#pragma unroll
            for (int mt = 0; mt < MT; mt++) {
                uint32_t al[4];
                ldsm4(al, bo + ASZ + aOff + mt * 16 * ROWB + kb);
#pragma unroll
                for (int nt = 0; nt < 4; nt++)
                    mma_bf16(acc[mt][nt], al, &bh4[nt >> 1][(nt & 1) * 2]);
            }
        }
    }

    int er = m0 + wm + (lane >> 2);
    int ec = n0 + wn + (lane & 3) * 2;
#pragma unroll
    for (int mt = 0; mt < MT; mt++) {
#pragma unroll
        for (int nt = 0; nt < 4; nt++) {
            int col = ec + nt * 8;
            if (col >= Nlim) continue;
            float* p0 = C + (size_t)(er + mt * 16) * ldc + col;
            float* p1 = p0 + 8 * ldc;
            float d0 = acc[mt][nt][0], d1 = acc[mt][nt][1];
            float d2 = acc[mt][nt][2], d3 = acc[mt][nt][3];
            if (EPI == 3) {
                atomicAdd(p0, d0); atomicAdd(p0 + 1, d1);
                atomicAdd(p1, d2); atomicAdd(p1 + 1, d3);
                continue;
            }
            if (EPI == 1) {
                float b0 = aux[col], b1 = aux[col + 1];
                d0 += b0; d1 += b1; d2 += b0; d3 += b1;
                d0 = (d0 > 20.f) ? d0 : log1pf(__expf(d0));
                d1 = (d1 > 20.f) ? d1 : log1pf(__expf(d1));
                d2 = (d2 > 20.f) ? d2 : log1pf(__expf(d2));
                d3 = (d3 > 20.f) ? d3 : log1pf(__expf(d3));
            } else if (EPI == 2) {
                float2 o0 = *(float2*)p0, o1 = *(float2*)p1;
                d0 += o0.x; d1 += o0.y; d2 += o1.x; d3 += o1.y;
            }
            *(float2*)p0 = make_float2(d0, d1);
            *(float2*)p1 = make_float2(d2, d3);
        }
    }
}

// ---------------- fp16 asymmetric 2-term GEMM (lm_head): 128x128 tile ----------------
// C = (Ah + Al) * Bh^T ; A in 2 fp16 digits (22-bit effective), B single fp16.
__global__ __launch_bounds__(256, 2) void h2gemm_k(
    const __half* __restrict__ Ah, const __half* __restrict__ Al,
    const __half* __restrict__ Bh,
    float* __restrict__ C, int K, int ldc)
{
    constexpr int ASZ   = 128 * ROWB;        // one array per chunk: 10240 B
    constexpr int BUFSZ = 3 * ASZ;           // Ah, Al, Bh

    extern __shared__ char dynsm[];
    uint32_t base = smem_u32(dynsm);

    int tid = threadIdx.x, lane = tid & 31, wid = tid >> 5;
    int m0 = blockIdx.x * 128, n0 = blockIdx.y * 128;
    int wm = (wid & 1) * 64, wn = (wid >> 1) * 32;

    int lr = tid >> 2;
    int lk = (tid & 3) * 8;

    const __half* gAh0 = Ah + (size_t)(m0 + lr) * K + lk;
    const __half* gAl0 = Al + (size_t)(m0 + lr) * K + lk;
    const __half* gBh0 = Bh + (size_t)(n0 + lr) * K + lk;
    const size_t rstep = (size_t)64 * K;

    uint32_t st0 = (uint32_t)(lr * ROWB + lk * 2);
    uint32_t st1 = st0 + 64 * ROWB;

    uint32_t aOff = (uint32_t)((wm + (lane & 15)) * ROWB + (lane >> 4) * 16);
    uint32_t bOff4 = (uint32_t)((wn + ((lane >> 4) << 3) + (lane & 7)) * ROWB
                                + ((lane >> 3) & 1) * 16);

    float acc[4][4][4];
#pragma unroll
    for (int i = 0; i < 4; i++)
#pragma unroll
        for (int j = 0; j < 4; j++)
#pragma unroll
            for (int r = 0; r < 4; r++) acc[i][j][r] = 0.f;

    int nchunk = K >> 5;

    auto prefetch = [&](int kc, int buf) {
        int ko = kc * 32;
        uint32_t bo = base + buf * BUFSZ;
        cpa16(bo + st0,           gAh0 + ko);  cpa16(bo + st1,           gAh0 + rstep + ko);
        cpa16(bo + ASZ + st0,     gAl0 + ko);  cpa16(bo + ASZ + st1,     gAl0 + rstep + ko);
        cpa16(bo + 2 * ASZ + st0, gBh0 + ko);  cpa16(bo + 2 * ASZ + st1, gBh0 + rstep + ko);
    };

    prefetch(0, 0);
    CP_COMMIT();

    for (int kc = 0; kc < nchunk; kc++) {
        CP_WAIT0();
        __syncthreads();
        if (kc + 1 < nchunk) prefetch(kc + 1, (kc + 1) & 1);
        CP_COMMIT();

        uint32_t bo = base + (kc & 1) * BUFSZ;
#pragma unroll
        for (int kk = 0; kk < 2; kk++) {
            uint32_t kb = kk * 32;
            uint32_t bh4[2][4];
#pragma unroll
            for (int p = 0; p < 2; p++)
                ldsm4(bh4[p], bo + 2 * ASZ + bOff4 + p * 16 * ROWB + kb);
#pragma unroll
            for (int mt = 0; mt < 4; mt++) {
                uint32_t ah[4];
                ldsm4(ah, bo + aOff + mt * 16 * ROWB + kb);
#pragma unroll
                for (int nt = 0; nt < 4; nt++)
                    mma_f16(acc[mt][nt], ah, &bh4[nt >> 1][(nt & 1) * 2]);
            }
#pragma unroll
            for (int mt = 0; mt < 4; mt++) {
                uint32_t al[4];
                ldsm4(al, bo + ASZ + aOff + mt * 16 * ROWB + kb);
#pragma unroll
                for (int nt = 0; nt < 4; nt++)
                    mma_f16(acc[mt][nt], al, &bh4[nt >> 1][(nt & 1) * 2]);
            }
        }
    }

    int er = m0 + wm + (lane >> 2);
    int ec = n0 + wn + (lane & 3) * 2;
#pragma unroll
    for (int mt = 0; mt < 4; mt++) {
#pragma unroll
        for (int nt = 0; nt < 4; nt++) {
            float* p0 = C + (size_t)(er + mt * 16) * ldc + ec + nt * 8;
            float* p1 = p0 + 8 * ldc;
            *(float2*)p0 = make_float2(acc[mt][nt][0], acc[mt][nt][1]);
            *(float2*)p1 = make_float2(acc[mt][nt][2], acc[mt][nt][3]);
        }
    }
}

// ---------------- selective scan ----------------
__global__ void scan1_k(const float* __restrict__ delta, const float* __restrict__ xb,
                        const float* __restrict__ dbc, const float* __restrict__ A_log,
                        float* __restrict__ cp, float* __restrict__ cs) {
    int i = blockIdx.x * blockDim.x + threadIdx.x;
    if (i >= NCHUNK * ED) return;
    int c = i / ED, e = i % ED;
    float A[NST], h[NST], p[NST];
#pragma unroll
    for (int n = 0; n < NST; n++) {
        A[n] = -__expf(A_log[e * NST + n]);
        h[n] = 0.f; p[n] = 1.f;
    }
    int t0 = c * CHUNK;
    for (int t = t0; t < t0 + CHUNK; t++) {
        float d  = delta[(size_t)t * ED + e];
        float xv = xb[(size_t)t * ED + e];
        float dx = d * xv;
        const float* Bt = dbc + (size_t)t * DXP + DTR;
#pragma unroll
        for (int n = 0; n < NST; n++) {
            float a = __expf(d * A[n]);
            p[n] *= a;
            h[n] = fmaf(a, h[n], dx * Bt[n]);
        }
    }
    size_t o = (size_t)i * NST;
#pragma unroll
    for (int n = 0; n < NST; n++) { cp[o + n] = p[n]; cs[o + n] = h[n]; }
}

__global__ void carry_k(const float* __restrict__ cp, const float* __restrict__ cs,
                        float* __restrict__ cc) {
    int i = blockIdx.x * blockDim.x + threadIdx.x;
    if (i >= ED * NST) return;
    float H = 0.f;
    for (int c = 0; c < NCHUNK; c++) {
        size_t idx = (size_t)c * ED * NST + i;
        cc[idx] = H;
        H = fmaf(cp[idx], H, cs[idx]);
    }
}

__global__ void scan2_k(const float* __restrict__ delta, const float* __restrict__ xb,
                        const float* __restrict__ dbc, const float* __restrict__ A_log,
                        const float* __restrict__ cc, const float* __restrict__ Dp,
                        const float* __restrict__ xz,
                        __nv_bfloat16* __restrict__ yzh, __nv_bfloat16* __restrict__ yzl) {
    int i = blockIdx.x * blockDim.x + threadIdx.x;
    if (i >= NCHUNK * ED) return;
    int c = i / ED, e = i % ED;
    float A[NST], h[NST];
#pragma unroll
    for (int n = 0; n < NST; n++) {
        A[n] = -__expf(A_log[e * NST + n]);
        h[n] = cc[(size_t)i * NST + n];
    }
    float Dv = Dp[e];
    int t0 = c * CHUNK;
    for (int t = t0; t < t0 + CHUNK; t++) {
        float d  = delta[(size_t)t * ED + e];
        float xv = xb[(size_t)t * ED + e];
        float dx = d * xv;
        const float* Bt = dbc + (size_t)t * DXP + DTR;
        const float* Ct = dbc + (size_t)t * DXP + DTR + NST;
        float y = 0.f;
#pragma unroll
        for (int n = 0; n < NST; n++) {
            float a = __expf(d * A[n]);
            h[n] = fmaf(a, h[n], dx * Bt[n]);
            y = fmaf(h[n], Ct[n], y);
        }
        float zv = xz[(size_t)t * (2 * ED) + ED + e];
        float sz = zv / (1.f + __expf(-zv));
        float v = (y + xv * Dv) * sz;
        __nv_bfloat16 hb = __float2bfloat16(v);
        yzh[(size_t)t * ED + e] = hb;
        yzl[(size_t)t * ED + e] = __float2bfloat16(v - __bfloat162float(hb));
    }
}

// ---------------- host orchestration ----------------
extern "C" void kernel_launch(void* const* d_in, const int* in_sizes, int n_in,
                              void* d_out, int out_size) {
    const int*   tokens  = (const int*)d_in[0];
    const float* emb     = (const float*)d_in[1];
    const float* norm_w  = (const float*)d_in[2];
    const float* in_proj = (const float*)d_in[3];
    const float* conv_w  = (const float*)d_in[4];
    const float* conv_b  = (const float*)d_in[5];
    const float* x_proj  = (const float*)d_in[6];
    const float* dt_w    = (const float*)d_in[7];
    const float* dt_b    = (const float*)d_in[8];
    const float* A_log   = (const float*)d_in[9];
    const float* Dp      = (const float*)d_in[10];
    const float* out_prj = (const float*)d_in[11];
    const float* norm_f  = (const float*)d_in[12];
    const float* lm_head = (const float*)d_in[13];
    float* logits = (float*)d_out;

    float *x, *xz, *xb, *dbc, *delta, *cp, *cs, *cc;
    __nv_bfloat16 *ah, *al, *dh, *dl, *wh, *wl;
    cudaGetSymbolAddress((void**)&x,     g_x);
    cudaGetSymbolAddress((void**)&xz,    g_xz);
    cudaGetSymbolAddress((void**)&xb,    g_xb);
    cudaGetSymbolAddress((void**)&dbc,   g_dbc);
    cudaGetSymbolAddress((void**)&delta, g_delta);
    cudaGetSymbolAddress((void**)&cp,    g_cp);
    cudaGetSymbolAddress((void**)&cs,    g_cs);
    cudaGetSymbolAddress((void**)&cc,    g_cc);
    cudaGetSymbolAddress((void**)&ah,    g_ah);
    cudaGetSymbolAddress((void**)&al,    g_al);
    cudaGetSymbolAddress((void**)&dh,    g_dh);
    cudaGetSymbolAddress((void**)&dl,    g_dl);
    cudaGetSymbolAddress((void**)&wh,    g_wh);
    cudaGetSymbolAddress((void**)&wl,    g_wl);

    const int SM4 = 2 * (2 * 4 * 32 * ROWB + 2 * 128 * ROWB);   // 81920
    const int SM2 = 2 * (2 * 2 * 32 * ROWB + 2 * 128 * ROWB);   // 61440
    const int SM1 = 2 * (2 * 1 * 32 * ROWB + 2 * 128 * ROWB);   // 51200
    const int SMH = 2 * 3 * 128 * ROWB;                          // 61440
    static bool attr_done = false;
    if (!attr_done) {
        cudaFuncSetAttribute(hgemm_k<2,0>, cudaFuncAttributeMaxDynamicSharedMemorySize, SM2);
        cudaFuncSetAttribute(hgemm_k<2,2>, cudaFuncAttributeMaxDynamicSharedMemorySize, SM2);
        cudaFuncSetAttribute(hgemm_k<1,3>, cudaFuncAttributeMaxDynamicSharedMemorySize, SM1);
        cudaFuncSetAttribute(hgemm_k<4,1>, cudaFuncAttributeMaxDynamicSharedMemorySize, SM4);
        cudaFuncSetAttribute(h2gemm_k,     cudaFuncAttributeMaxDynamicSharedMemorySize, SMH);
        attr_done = true;
    }

    embed_k<<<(L * D + 255) / 256, 256>>>(tokens, emb, x);

    for (int l = 0; l < NL; l++) {
        rmsnorm_split_k<<<L, 256>>>(x, norm_w + l * D, ah, al);

        // xz = xn @ in_proj^T
        int nwi = 2 * ED * D;
        split4_k<<<(nwi / 4 + 255) / 256, 256>>>(
            (const float4*)(in_proj + (size_t)l * nwi), (__nv_bfloat162*)wh, (__nv_bfloat162*)wl, nwi / 4);
        hgemm_k<2,0><<<dim3(L / 64, 2 * ED / 128), 256, SM2>>>(
            ah, al, wh, wl, xz, D, D, 2 * ED, 2 * ED, nullptr);

        // conv + silu (also emits bf16 hi/lo of xb into ah/al)
        conv_silu_split_k<<<(L * ED + 255) / 256, 256>>>(
            xz, conv_w + (size_t)l * ED * DCONV, conv_b + l * ED, xb, ah, al);

        // dbc = xb @ x_proj^T  (N=80 padded to 128, split-K=2 with atomics)
        split_pad_k<<<(128 * ED + 255) / 256, 256>>>(
            x_proj + (size_t)l * DXP * ED, wh, wl, 128, ED, DXP, ED, ED);
        cudaMemsetAsync(dbc, 0, (size_t)L * DXP * sizeof(float));
        hgemm_k<1,3><<<dim3(L / 32, 1, 2), 256, SM1>>>(
            ah, al, wh, wl, dbc, ED / 2, ED, DXP, DXP, nullptr);

        // delta = softplus(dbc[:, :48] @ dt_w^T + dt_b)   (K=48 padded to 64)
        split_pad_k<<<(L * 64 + 255) / 256, 256>>>(dbc, dh, dl, L, 64, L, DTR, DXP);
        split_pad_k<<<(ED * 64 + 255) / 256, 256>>>(
            dt_w + (size_t)l * ED * DTR, wh, wl, ED, 64, ED, DTR, DTR);
        hgemm_k<4,1><<<dim3(L / 128, ED / 128), 256, SM4>>>(
            dh, dl, wh, wl, delta, 64, 64, ED, ED, dt_b + l * ED);

        // selective scan (writes gated output as bf16 hi/lo into ah/al)
        scan1_k<<<(NCHUNK * ED) / 256, 256>>>(delta, xb, dbc,
                                              A_log + (size_t)l * ED * NST, cp, cs);
        carry_k<<<(ED * NST) / 256, 256>>>(cp, cs, cc);
        scan2_k<<<(NCHUNK * ED) / 256, 256>>>(delta, xb, dbc,
                                              A_log + (size_t)l * ED * NST, cc,
                                              Dp + l * ED, xz, ah, al);

        // x += yz @ out_proj^T
        int nwo = D * ED;
        split4_k<<<(nwo / 4 + 255) / 256, 256>>>(
            (const float4*)(out_prj + (size_t)l * nwo), (__nv_bfloat162*)wh, (__nv_bfloat162*)wl, nwo / 4);
        hgemm_k<2,2><<<dim3(L / 64, D / 128), 256, SM2>>>(
            ah, al, wh, wl, x, ED, ED, D, D, nullptr);
    }

    // final norm -> fp16 2-digit activations; lm_head weights -> fp16; 2-term GEMM
    rmsnorm_splith_k<<<L, 256>>>(x, norm_f, (__half*)ah, (__half*)al);
    int nwl = VOCAB * D;
    tofp16_k<<<(nwl / 4 + 255) / 256, 256>>>(
        (const float4*)lm_head, (__half2*)wh, nwl / 4);
    h2gemm_k<<<dim3(L / 128, VOCAB / 128), 256, SMH>>>(
        (const __half*)ah, (const __half*)al, (const __half*)wh, logits, D, VOCAB);
}

// round 10
// speedup vs baseline: 2.0756x; 1.1317x over previous
#include <cuda_runtime.h>
#include <cuda_bf16.h>
#include <cuda_fp16.h>
#include <math.h>
#include <cstdint>

// ---------------- problem constants ----------------
#define L       2048
#define D       768
#define ED      1536
#define NL      4
#define NST     16
#define DTR     48
#define DXP     80
#define VOCAB   32000
#define DCONV   4
#define CHUNK   64
#define NCHUNK  (L / CHUNK)

// ---------------- scratch ----------------
__device__ __align__(256) float g_x    [L * D];
__device__ __align__(256) float g_xz   [L * 2 * ED];
__device__ __align__(256) float g_xb   [L * ED];
__device__ __align__(256) float g_dbc  [L * DXP];
__device__ __align__(256) float g_delta[L * ED];
__device__ __align__(256) float g_cp   [NCHUNK * ED * NST];
__device__ __align__(256) float g_cs   [NCHUNK * ED * NST];
__device__ __align__(256) float g_cc   [NCHUNK * ED * NST];
__device__ __align__(256) __half g_ah[L * ED];
__device__ __align__(256) __half g_al[L * ED];
__device__ __align__(256) __half g_dh[L * 64];
__device__ __align__(256) __half g_dl[L * 64];
__device__ __align__(256) __half g_wh[VOCAB * D];

// ---------------- helpers ----------------
__device__ __forceinline__ uint32_t smem_u32(const void* p) {
    uint32_t a;
    asm("{ .reg .u64 t; cvta.to.shared.u64 t, %1; cvt.u32.u64 %0, t; }" : "=r"(a) : "l"(p));
    return a;
}
__device__ __forceinline__ void ldsm4(uint32_t* r, uint32_t addr) {
    asm volatile("ldmatrix.sync.aligned.m8n8.x4.shared.b16 {%0,%1,%2,%3}, [%4];"
                 : "=r"(r[0]), "=r"(r[1]), "=r"(r[2]), "=r"(r[3]) : "r"(addr));
}
__device__ __forceinline__ void mma_f16(float* d, const uint32_t* a, const uint32_t* b) {
    asm volatile(
        "mma.sync.aligned.m16n8k16.row.col.f32.f16.f16.f32 "
        "{%0,%1,%2,%3}, {%4,%5,%6,%7}, {%8,%9}, {%0,%1,%2,%3};"
        : "+f"(d[0]), "+f"(d[1]), "+f"(d[2]), "+f"(d[3])
        : "r"(a[0]), "r"(a[1]), "r"(a[2]), "r"(a[3]), "r"(b[0]), "r"(b[1]));
}
__device__ __forceinline__ void cpa16(uint32_t d, const void* s) {
    asm volatile("cp.async.cg.shared.global [%0], [%1], 16;" :: "r"(d), "l"(s));
}
#define CP_COMMIT() asm volatile("cp.async.commit_group;" ::: "memory")
#define CP_WAIT0()  asm volatile("cp.async.wait_group 0;" ::: "memory")

// ---------------- embedding ----------------
__global__ void embed_k(const int* __restrict__ tok, const float* __restrict__ emb,
                        float* __restrict__ x) {
    int i = blockIdx.x * blockDim.x + threadIdx.x;
    if (i >= L * D) return;
    int t = i / D, d = i % D;
    x[i] = emb[(size_t)tok[t] * D + d];
}

// ---------------- fp32 -> fp16 flat convert ----------------
__global__ void tofp16_k(const float4* __restrict__ src, __half2* __restrict__ dst, int n4) {
    int i = blockIdx.x * blockDim.x + threadIdx.x;
    if (i >= n4) return;
    float4 v = src[i];
    dst[2 * i]     = __floats2half2_rn(v.x, v.y);
    dst[2 * i + 1] = __floats2half2_rn(v.z, v.w);
}

// fp32 -> fp16 padded convert (single digit): dst [Mdst, Kp] from src [Msrc, Kin] stride Ssrc
__global__ void tofp16_pad_k(const float* __restrict__ src, __half* __restrict__ dst,
                             int Mdst, int Kp, int Msrc, int Kin, int Ssrc) {
    int i = blockIdx.x * blockDim.x + threadIdx.x;
    if (i >= Mdst * Kp) return;
    int r = i / Kp, c = i % Kp;
    float v = (r < Msrc && c < Kin) ? src[(size_t)r * Ssrc + c] : 0.f;
    dst[i] = __float2half_rn(v);
}

// fp32 -> fp16 2-digit padded split
__global__ void splith_pad_k(const float* __restrict__ src, __half* __restrict__ hi,
                             __half* __restrict__ lo,
                             int Mdst, int Kp, int Msrc, int Kin, int Ssrc) {
    int i = blockIdx.x * blockDim.x + threadIdx.x;
    if (i >= Mdst * Kp) return;
    int r = i / Kp, c = i % Kp;
    float v = (r < Msrc && c < Kin) ? src[(size_t)r * Ssrc + c] : 0.f;
    __half h = __float2half_rn(v);
    hi[i] = h;
    lo[i] = __float2half_rn(v - __half2float(h));
}

// ---------------- RMSNorm -> fp16 hi/lo ----------------
__global__ void rmsnorm_splith_k(const float* __restrict__ x, const float* __restrict__ w,
                                 __half* __restrict__ oh, __half* __restrict__ ol) {
    int t = blockIdx.x;
    const float* xr = x + (size_t)t * D;
    float s = 0.f;
    for (int d = threadIdx.x; d < D; d += 256) { float v = xr[d]; s += v * v; }
    __shared__ float red[256];
    red[threadIdx.x] = s;
    __syncthreads();
    for (int o = 128; o > 0; o >>= 1) {
        if (threadIdx.x < o) red[threadIdx.x] += red[threadIdx.x + o];
        __syncthreads();
    }
    float inv = rsqrtf(red[0] / (float)D + 1e-5f);
    for (int d = threadIdx.x; d < D; d += 256) {
        float v = xr[d] * inv * w[d];
        __half h = __float2half_rn(v);
        oh[(size_t)t * D + d] = h;
        ol[(size_t)t * D + d] = __float2half_rn(v - __half2float(h));
    }
}

// ---------------- conv1d + silu, fused fp16 hi/lo split of output ----------------
__global__ void conv_silu_split_k(const float* __restrict__ xz, const float* __restrict__ w,
                                  const float* __restrict__ b, float* __restrict__ xb,
                                  __half* __restrict__ oh, __half* __restrict__ ol) {
    int i = blockIdx.x * blockDim.x + threadIdx.x;
    if (i >= L * ED) return;
    int t = i / ED, e = i % ED;
    const float* wr = w + e * DCONV;
    float acc = b[e];
#pragma unroll
    for (int j = 0; j < DCONV; j++) {
        int tt = t - (DCONV - 1) + j;
        if (tt >= 0) acc = fmaf(xz[(size_t)tt * (2 * ED) + e], wr[j], acc);
    }
    float v = acc / (1.f + __expf(-acc));
    xb[i] = v;
    __half h = __float2half_rn(v);
    oh[i] = h;
    ol[i] = __float2half_rn(v - __half2float(h));
}

// ---------------- fp16 asymmetric 2-term GEMM ----------------
// C[(MT*32) x 128] tile. C = (Ah + Al) * Bh^T (fp32 accum).
// EPI: 0 = store, 1 = softplus(acc + aux[n]), 2 = C += acc, 3 = atomicAdd (split-K).
#define ROWB 80

template<int MT, int EPI>
__global__ __launch_bounds__(256, 2) void h2gemm_k(
    const __half* __restrict__ Ah, const __half* __restrict__ Al,
    const __half* __restrict__ Bh,
    float* __restrict__ C, int K, int strideK, int ldc, int Nlim,
    const float* __restrict__ aux)
{
    constexpr int ASZ   = MT * 32 * ROWB;
    constexpr int BSZ   = 128 * ROWB;
    constexpr int BUFSZ = 2 * ASZ + BSZ;

    extern __shared__ char dynsm[];
    uint32_t base = smem_u32(dynsm);

    int tid = threadIdx.x, lane = tid & 31, wid = tid >> 5;
    int m0 = blockIdx.x * (MT * 32), n0 = blockIdx.y * 128;
    int wm = (wid & 1) * (MT * 16), wn = (wid >> 1) * 32;
    int koff = blockIdx.z * K;

    int lr = tid >> 2;
    int lk = (tid & 3) * 8;

    const __half* gAh0 = Ah + (size_t)(m0 + lr) * strideK + koff + lk;
    const __half* gAl0 = Al + (size_t)(m0 + lr) * strideK + koff + lk;
    const __half* gAh1 = (MT == 4) ? gAh0 + (size_t)64 * strideK : gAh0;
    const __half* gAl1 = (MT == 4) ? gAl0 + (size_t)64 * strideK : gAl0;
    const __half* gBh0 = Bh + (size_t)(n0 + lr) * strideK + koff + lk;
    const __half* gBh1 = gBh0 + (size_t)64 * strideK;

    uint32_t st0 = (uint32_t)(lr * ROWB + lk * 2);
    uint32_t st1 = st0 + 64 * ROWB;

    uint32_t aOff = (uint32_t)((wm + (lane & 15)) * ROWB + (lane >> 4) * 16);
    uint32_t bOff4 = (uint32_t)((wn + ((lane >> 4) << 3) + (lane & 7)) * ROWB
                                + ((lane >> 3) & 1) * 16);

    float acc[MT][4][4];
#pragma unroll
    for (int i = 0; i < MT; i++)
#pragma unroll
        for (int j = 0; j < 4; j++)
#pragma unroll
            for (int r = 0; r < 4; r++) acc[i][j][r] = 0.f;

    int nchunk = K >> 5;

    auto prefetch = [&](int kc, int buf) {
        int ko = kc * 32;
        uint32_t bo = base + buf * BUFSZ;
        if (MT == 4) {
            cpa16(bo + st0, gAh0 + ko);        cpa16(bo + st1, gAh1 + ko);
            cpa16(bo + ASZ + st0, gAl0 + ko);  cpa16(bo + ASZ + st1, gAl1 + ko);
        } else if (MT == 2) {
            cpa16(bo + st0, gAh0 + ko);
            cpa16(bo + ASZ + st0, gAl0 + ko);
        } else {
            if (lr < 32) {
                cpa16(bo + st0, gAh0 + ko);
                cpa16(bo + ASZ + st0, gAl0 + ko);
            }
        }
        cpa16(bo + 2 * ASZ + st0, gBh0 + ko);
        cpa16(bo + 2 * ASZ + st1, gBh1 + ko);
    };

    prefetch(0, 0);
    CP_COMMIT();

    for (int kc = 0; kc < nchunk; kc++) {
        CP_WAIT0();
        __syncthreads();
        if (kc + 1 < nchunk) prefetch(kc + 1, (kc + 1) & 1);
        CP_COMMIT();

        uint32_t bo = base + (kc & 1) * BUFSZ;
#pragma unroll
        for (int kk = 0; kk < 2; kk++) {
            uint32_t kb = kk * 32;
            uint32_t bh4[2][4];
#pragma unroll
            for (int p = 0; p < 2; p++)
                ldsm4(bh4[p], bo + 2 * ASZ + bOff4 + p * 16 * ROWB + kb);
#pragma unroll
            for (int mt = 0; mt < MT; mt++) {
                uint32_t ah[4];
                ldsm4(ah, bo + aOff + mt * 16 * ROWB + kb);
#pragma unroll
                for (int nt = 0; nt < 4; nt++)
                    mma_f16(acc[mt][nt], ah, &bh4[nt >> 1][(nt & 1) * 2]);
            }
#pragma unroll
            for (int mt = 0; mt < MT; mt++) {
                uint32_t al[4];
                ldsm4(al, bo + ASZ + aOff + mt * 16 * ROWB + kb);
#pragma unroll
                for (int nt = 0; nt < 4; nt++)
                    mma_f16(acc[mt][nt], al, &bh4[nt >> 1][(nt & 1) * 2]);
            }
        }
    }

    int er = m0 + wm + (lane >> 2);
    int ec = n0 + wn + (lane & 3) * 2;
#pragma unroll
    for (int mt = 0; mt < MT; mt++) {
#pragma unroll
        for (int nt = 0; nt < 4; nt++) {
            int col = ec + nt * 8;
            if (col >= Nlim) continue;
            float* p0 = C + (size_t)(er + mt * 16) * ldc + col;
            float* p1 = p0 + 8 * ldc;
            float d0 = acc[mt][nt][0], d1 = acc[mt][nt][1];
            float d2 = acc[mt][nt][2], d3 = acc[mt][nt][3];
            if (EPI == 3) {
                atomicAdd(p0, d0); atomicAdd(p0 + 1, d1);
                atomicAdd(p1, d2); atomicAdd(p1 + 1, d3);
                continue;
            }
            if (EPI == 1) {
                float b0 = aux[col], b1 = aux[col + 1];
                d0 += b0; d1 += b1; d2 += b0; d3 += b1;
                d0 = (d0 > 20.f) ? d0 : log1pf(__expf(d0));
                d1 = (d1 > 20.f) ? d1 : log1pf(__expf(d1));
                d2 = (d2 > 20.f) ? d2 : log1pf(__expf(d2));
                d3 = (d3 > 20.f) ? d3 : log1pf(__expf(d3));
            } else if (EPI == 2) {
                float2 o0 = *(float2*)p0, o1 = *(float2*)p1;
                d0 += o0.x; d1 += o0.y; d2 += o1.x; d3 += o1.y;
            }
            *(float2*)p0 = make_float2(d0, d1);
            *(float2*)p1 = make_float2(d2, d3);
        }
    }
}

// ---------------- selective scan ----------------
__global__ void scan1_k(const float* __restrict__ delta, const float* __restrict__ xb,
                        const float* __restrict__ dbc, const float* __restrict__ A_log,
                        float* __restrict__ cp, float* __restrict__ cs) {
    int i = blockIdx.x * blockDim.x + threadIdx.x;
    if (i >= NCHUNK * ED) return;
    int c = i / ED, e = i % ED;
    float A[NST], h[NST], p[NST];
#pragma unroll
    for (int n = 0; n < NST; n++) {
        A[n] = -__expf(A_log[e * NST + n]);
        h[n] = 0.f; p[n] = 1.f;
    }
    int t0 = c * CHUNK;
    for (int t = t0; t < t0 + CHUNK; t++) {
        float d  = delta[(size_t)t * ED + e];
        float xv = xb[(size_t)t * ED + e];
        float dx = d * xv;
        const float* Bt = dbc + (size_t)t * DXP + DTR;
#pragma unroll
        for (int n = 0; n < NST; n++) {
            float a = __expf(d * A[n]);
            p[n] *= a;
            h[n] = fmaf(a, h[n], dx * Bt[n]);
        }
    }
    size_t o = (size_t)i * NST;
#pragma unroll
    for (int n = 0; n < NST; n++) { cp[o + n] = p[n]; cs[o + n] = h[n]; }
}

__global__ void carry_k(const float* __restrict__ cp, const float* __restrict__ cs,
                        float* __restrict__ cc) {
    int i = blockIdx.x * blockDim.x + threadIdx.x;
    if (i >= ED * NST) return;
    float H = 0.f;
    for (int c = 0; c < NCHUNK; c++) {
        size_t idx = (size_t)c * ED * NST + i;
        cc[idx] = H;
        H = fmaf(cp[idx], H, cs[idx]);
    }
}

__global__ void scan2_k(const float* __restrict__ delta, const float* __restrict__ xb,
                        const float* __restrict__ dbc, const float* __restrict__ A_log,
                        const float* __restrict__ cc, const float* __restrict__ Dp,
                        const float* __restrict__ xz,
                        __half* __restrict__ yzh, __half* __restrict__ yzl) {
    int i = blockIdx.x * blockDim.x + threadIdx.x;
    if (i >= NCHUNK * ED) return;
    int c = i / ED, e = i % ED;
    float A[NST], h[NST];
#pragma unroll
    for (int n = 0; n < NST; n++) {
        A[n] = -__expf(A_log[e * NST + n]);
        h[n] = cc[(size_t)i * NST + n];
    }
    float Dv = Dp[e];
    int t0 = c * CHUNK;
    for (int t = t0; t < t0 + CHUNK; t++) {
        float d  = delta[(size_t)t * ED + e];
        float xv = xb[(size_t)t * ED + e];
        float dx = d * xv;
        const float* Bt = dbc + (size_t)t * DXP + DTR;
        const float* Ct = dbc + (size_t)t * DXP + DTR + NST;
        float y = 0.f;
#pragma unroll
        for (int n = 0; n < NST; n++) {
            float a = __expf(d * A[n]);
            h[n] = fmaf(a, h[n], dx * Bt[n]);
            y = fmaf(h[n], Ct[n], y);
        }
        float zv = xz[(size_t)t * (2 * ED) + ED + e];
        float sz = zv / (1.f + __expf(-zv));
        float v = (y + xv * Dv) * sz;
        __half hb = __float2half_rn(v);
        yzh[(size_t)t * ED + e] = hb;
        yzl[(size_t)t * ED + e] = __float2half_rn(v - __half2float(hb));
    }
}

// ---------------- host orchestration ----------------
extern "C" void kernel_launch(void* const* d_in, const int* in_sizes, int n_in,
                              void* d_out, int out_size) {
    const int*   tokens  = (const int*)d_in[0];
    const float* emb     = (const float*)d_in[1];
    const float* norm_w  = (const float*)d_in[2];
    const float* in_proj = (const float*)d_in[3];
    const float* conv_w  = (const float*)d_in[4];
    const float* conv_b  = (const float*)d_in[5];
    const float* x_proj  = (const float*)d_in[6];
    const float* dt_w    = (const float*)d_in[7];
    const float* dt_b    = (const float*)d_in[8];
    const float* A_log   = (const float*)d_in[9];
    const float* Dp      = (const float*)d_in[10];
    const float* out_prj = (const float*)d_in[11];
    const float* norm_f  = (const float*)d_in[12];
    const float* lm_head = (const float*)d_in[13];
    float* logits = (float*)d_out;

    float *x, *xz, *xb, *dbc, *delta, *cp, *cs, *cc;
    __half *ah, *al, *dh, *dl, *wh;
    cudaGetSymbolAddress((void**)&x,     g_x);
    cudaGetSymbolAddress((void**)&xz,    g_xz);
    cudaGetSymbolAddress((void**)&xb,    g_xb);
    cudaGetSymbolAddress((void**)&dbc,   g_dbc);
    cudaGetSymbolAddress((void**)&delta, g_delta);
    cudaGetSymbolAddress((void**)&cp,    g_cp);
    cudaGetSymbolAddress((void**)&cs,    g_cs);
    cudaGetSymbolAddress((void**)&cc,    g_cc);
    cudaGetSymbolAddress((void**)&ah,    g_ah);
    cudaGetSymbolAddress((void**)&al,    g_al);
    cudaGetSymbolAddress((void**)&dh,    g_dh);
    cudaGetSymbolAddress((void**)&dl,    g_dl);
    cudaGetSymbolAddress((void**)&wh,    g_wh);

    const int SM4 = 2 * (2 * 4 * 32 * ROWB + 128 * ROWB);   // 61440
    const int SM2 = 2 * (2 * 2 * 32 * ROWB + 128 * ROWB);   // 40960
    const int SM1 = 2 * (2 * 1 * 32 * ROWB + 128 * ROWB);   // 30720
    static bool attr_done = false;
    if (!attr_done) {
        cudaFuncSetAttribute(h2gemm_k<2,0>, cudaFuncAttributeMaxDynamicSharedMemorySize, SM2);
        cudaFuncSetAttribute(h2gemm_k<2,2>, cudaFuncAttributeMaxDynamicSharedMemorySize, SM2);
        cudaFuncSetAttribute(h2gemm_k<1,3>, cudaFuncAttributeMaxDynamicSharedMemorySize, SM1);
        cudaFuncSetAttribute(h2gemm_k<4,1>, cudaFuncAttributeMaxDynamicSharedMemorySize, SM4);
        cudaFuncSetAttribute(h2gemm_k<4,0>, cudaFuncAttributeMaxDynamicSharedMemorySize, SM4);
        attr_done = true;
    }

    embed_k<<<(L * D + 255) / 256, 256>>>(tokens, emb, x);

    for (int l = 0; l < NL; l++) {
        rmsnorm_splith_k<<<L, 256>>>(x, norm_w + l * D, ah, al);

        // xz = xn @ in_proj^T
        int nwi = 2 * ED * D;
        tofp16_k<<<(nwi / 4 + 255) / 256, 256>>>(
            (const float4*)(in_proj + (size_t)l * nwi), (__half2*)wh, nwi / 4);
        h2gemm_k<2,0><<<dim3(L / 64, 2 * ED / 128), 256, SM2>>>(
            ah, al, wh, xz, D, D, 2 * ED, 2 * ED, nullptr);

        // conv + silu (also emits fp16 hi/lo of xb into ah/al)
        conv_silu_split_k<<<(L * ED + 255) / 256, 256>>>(
            xz, conv_w + (size_t)l * ED * DCONV, conv_b + l * ED, xb, ah, al);

        // dbc = xb @ x_proj^T  (N=80 padded to 128, split-K=2 with atomics)
        tofp16_pad_k<<<(128 * ED + 255) / 256, 256>>>(
            x_proj + (size_t)l * DXP * ED, wh, 128, ED, DXP, ED, ED);
        cudaMemsetAsync(dbc, 0, (size_t)L * DXP * sizeof(float));
        h2gemm_k<1,3><<<dim3(L / 32, 1, 2), 256, SM1>>>(
            ah, al, wh, dbc, ED / 2, ED, DXP, DXP, nullptr);

        // delta = softplus(dbc[:, :48] @ dt_w^T + dt_b)   (K=48 padded to 64)
        splith_pad_k<<<(L * 64 + 255) / 256, 256>>>(dbc, dh, dl, L, 64, L, DTR, DXP);
        tofp16_pad_k<<<(ED * 64 + 255) / 256, 256>>>(
            dt_w + (size_t)l * ED * DTR, wh, ED, 64, ED, DTR, DTR);
        h2gemm_k<4,1><<<dim3(L / 128, ED / 128), 256, SM4>>>(
            dh, dl, wh, delta, 64, 64, ED, ED, dt_b + l * ED);

        // selective scan (writes gated output as fp16 hi/lo into ah/al)
        scan1_k<<<(NCHUNK * ED) / 256, 256>>>(delta, xb, dbc,
                                              A_log + (size_t)l * ED * NST, cp, cs);
        carry_k<<<(ED * NST) / 256, 256>>>(cp, cs, cc);
        scan2_k<<<(NCHUNK * ED) / 256, 256>>>(delta, xb, dbc,
                                              A_log + (size_t)l * ED * NST, cc,
                                              Dp + l * ED, xz, ah, al);

        // x += yz @ out_proj^T
        int nwo = D * ED;
        tofp16_k<<<(nwo / 4 + 255) / 256, 256>>>(
            (const float4*)(out_prj + (size_t)l * nwo), (__half2*)wh, nwo / 4);
        h2gemm_k<2,2><<<dim3(L / 64, D / 128), 256, SM2>>>(
            ah, al, wh, x, ED, ED, D, D, nullptr);
    }

    // final norm -> fp16 2-digit activations; lm_head -> fp16; 2-term GEMM
    rmsnorm_splith_k<<<L, 256>>>(x, norm_f, ah, al);
    int nwl = VOCAB * D;
    tofp16_k<<<(nwl / 4 + 255) / 256, 256>>>(
        (const float4*)lm_head, (__half2*)wh, nwl / 4);
    h2gemm_k<4,0><<<dim3(L / 128, VOCAB / 128), 256, SM4>>>(
        ah, al, wh, logits, D, D, VOCAB, VOCAB, nullptr);
}

// round 11
// speedup vs baseline: 2.6334x; 1.2687x over previous
#include <cuda_runtime.h>
#include <cuda_bf16.h>
#include <cuda_fp16.h>
#include <math.h>
#include <cstdint>

// ---------------- problem constants ----------------
#define L       2048
#define D       768
#define ED      1536
#define NL      4
#define NST     16
#define DTR     48
#define DXP     80
#define VOCAB   32000
#define DCONV   4
#define CHUNK   64
#define NCHUNK  (L / CHUNK)

// ---------------- scratch ----------------
__device__ __align__(256) float g_x    [L * D];
__device__ __align__(256) float g_xz   [L * 2 * ED];
__device__ __align__(256) float g_xb   [L * ED];
__device__ __align__(256) float g_dbc  [L * DXP];
__device__ __align__(256) float g_delta[L * ED];
__device__ __align__(256) float g_cp   [NCHUNK * ED * NST];
__device__ __align__(256) float g_cs   [NCHUNK * ED * NST];
__device__ __align__(256) float g_cc   [NCHUNK * ED * NST];
__device__ __align__(256) __half g_ah[L * ED];
__device__ __align__(256) __half g_dh[L * 64];
__device__ __align__(256) __half g_wh[VOCAB * D];

// ---------------- helpers ----------------
__device__ __forceinline__ uint32_t smem_u32(const void* p) {
    uint32_t a;
    asm("{ .reg .u64 t; cvta.to.shared.u64 t, %1; cvt.u32.u64 %0, t; }" : "=r"(a) : "l"(p));
    return a;
}
__device__ __forceinline__ void ldsm4(uint32_t* r, uint32_t addr) {
    asm volatile("ldmatrix.sync.aligned.m8n8.x4.shared.b16 {%0,%1,%2,%3}, [%4];"
                 : "=r"(r[0]), "=r"(r[1]), "=r"(r[2]), "=r"(r[3]) : "r"(addr));
}
__device__ __forceinline__ void mma_f16(float* d, const uint32_t* a, const uint32_t* b) {
    asm volatile(
        "mma.sync.aligned.m16n8k16.row.col.f32.f16.f16.f32 "
        "{%0,%1,%2,%3}, {%4,%5,%6,%7}, {%8,%9}, {%0,%1,%2,%3};"
        : "+f"(d[0]), "+f"(d[1]), "+f"(d[2]), "+f"(d[3])
        : "r"(a[0]), "r"(a[1]), "r"(a[2]), "r"(a[3]), "r"(b[0]), "r"(b[1]));
}
__device__ __forceinline__ void cpa16(uint32_t d, const void* s) {
    asm volatile("cp.async.cg.shared.global [%0], [%1], 16;" :: "r"(d), "l"(s));
}
#define CP_COMMIT() asm volatile("cp.async.commit_group;" ::: "memory")
#define CP_WAIT0()  asm volatile("cp.async.wait_group 0;" ::: "memory")

// ---------------- embedding ----------------
__global__ void embed_k(const int* __restrict__ tok, const float* __restrict__ emb,
                        float* __restrict__ x) {
    int i = blockIdx.x * blockDim.x + threadIdx.x;
    if (i >= L * D) return;
    int t = i / D, d = i % D;
    x[i] = emb[(size_t)tok[t] * D + d];
}

// ---------------- fp32 -> fp16 flat convert ----------------
__global__ void tofp16_k(const float4* __restrict__ src, __half2* __restrict__ dst, int n4) {
    int i = blockIdx.x * blockDim.x + threadIdx.x;
    if (i >= n4) return;
    float4 v = src[i];
    dst[2 * i]     = __floats2half2_rn(v.x, v.y);
    dst[2 * i + 1] = __floats2half2_rn(v.z, v.w);
}

// fp32 -> fp16 padded convert: dst [Mdst, Kp] from src [Msrc, Kin] stride Ssrc
__global__ void tofp16_pad_k(const float* __restrict__ src, __half* __restrict__ dst,
                             int Mdst, int Kp, int Msrc, int Kin, int Ssrc) {
    int i = blockIdx.x * blockDim.x + threadIdx.x;
    if (i >= Mdst * Kp) return;
    int r = i / Kp, c = i % Kp;
    float v = (r < Msrc && c < Kin) ? src[(size_t)r * Ssrc + c] : 0.f;
    dst[i] = __float2half_rn(v);
}

// ---------------- RMSNorm -> fp16 ----------------
__global__ void rmsnorm_h_k(const float* __restrict__ x, const float* __restrict__ w,
                            __half* __restrict__ oh) {
    int t = blockIdx.x;
    const float* xr = x + (size_t)t * D;
    float s = 0.f;
    for (int d = threadIdx.x; d < D; d += 256) { float v = xr[d]; s += v * v; }
    __shared__ float red[256];
    red[threadIdx.x] = s;
    __syncthreads();
    for (int o = 128; o > 0; o >>= 1) {
        if (threadIdx.x < o) red[threadIdx.x] += red[threadIdx.x + o];
        __syncthreads();
    }
    float inv = rsqrtf(red[0] / (float)D + 1e-5f);
    for (int d = threadIdx.x; d < D; d += 256)
        oh[(size_t)t * D + d] = __float2half_rn(xr[d] * inv * w[d]);
}

// ---------------- conv1d + silu, fused fp16 convert of output ----------------
__global__ void conv_silu_h_k(const float* __restrict__ xz, const float* __restrict__ w,
                              const float* __restrict__ b, float* __restrict__ xb,
                              __half* __restrict__ oh) {
    int i = blockIdx.x * blockDim.x + threadIdx.x;
    if (i >= L * ED) return;
    int t = i / ED, e = i % ED;
    const float* wr = w + e * DCONV;
    float acc = b[e];
#pragma unroll
    for (int j = 0; j < DCONV; j++) {
        int tt = t - (DCONV - 1) + j;
        if (tt >= 0) acc = fmaf(xz[(size_t)tt * (2 * ED) + e], wr[j], acc);
    }
    float v = acc / (1.f + __expf(-acc));
    xb[i] = v;
    oh[i] = __float2half_rn(v);
}

// ---------------- fp16 1-term GEMM ----------------
// C[(MT*32) x 128] tile. C = A * B^T (fp32 accum).
// EPI: 0 = store, 1 = softplus(acc + aux[n]), 2 = C += acc, 3 = atomicAdd (split-K).
#define ROWB 80

template<int MT, int EPI>
__global__ __launch_bounds__(256, 2) void h1gemm_k(
    const __half* __restrict__ A, const __half* __restrict__ B,
    float* __restrict__ C, int K, int strideK, int ldc, int Nlim,
    const float* __restrict__ aux)
{
    constexpr int ASZ   = MT * 32 * ROWB;
    constexpr int BSZ   = 128 * ROWB;
    constexpr int BUFSZ = ASZ + BSZ;

    extern __shared__ char dynsm[];
    uint32_t base = smem_u32(dynsm);

    int tid = threadIdx.x, lane = tid & 31, wid = tid >> 5;
    int m0 = blockIdx.x * (MT * 32), n0 = blockIdx.y * 128;
    int wm = (wid & 1) * (MT * 16), wn = (wid >> 1) * 32;
    int koff = blockIdx.z * K;

    int lr = tid >> 2;
    int lk = (tid & 3) * 8;

    const __half* gA0 = A + (size_t)(m0 + lr) * strideK + koff + lk;
    const __half* gA1 = (MT == 4) ? gA0 + (size_t)64 * strideK : gA0;
    const __half* gB0 = B + (size_t)(n0 + lr) * strideK + koff + lk;
    const __half* gB1 = gB0 + (size_t)64 * strideK;

    uint32_t st0 = (uint32_t)(lr * ROWB + lk * 2);
    uint32_t st1 = st0 + 64 * ROWB;

    uint32_t aOff = (uint32_t)((wm + (lane & 15)) * ROWB + (lane >> 4) * 16);
    uint32_t bOff4 = (uint32_t)((wn + ((lane >> 4) << 3) + (lane & 7)) * ROWB
                                + ((lane >> 3) & 1) * 16);

    float acc[MT][4][4];
#pragma unroll
    for (int i = 0; i < MT; i++)
#pragma unroll
        for (int j = 0; j < 4; j++)
#pragma unroll
            for (int r = 0; r < 4; r++) acc[i][j][r] = 0.f;

    int nchunk = K >> 5;

    auto prefetch = [&](int kc, int buf) {
        int ko = kc * 32;
        uint32_t bo = base + buf * BUFSZ;
        if (MT == 4) {
            cpa16(bo + st0, gA0 + ko);
            cpa16(bo + st1, gA1 + ko);
        } else if (MT == 2) {
            cpa16(bo + st0, gA0 + ko);
        } else {
            if (lr < 32) cpa16(bo + st0, gA0 + ko);
        }
        cpa16(bo + ASZ + st0, gB0 + ko);
        cpa16(bo + ASZ + st1, gB1 + ko);
    };

    prefetch(0, 0);
    CP_COMMIT();

    for (int kc = 0; kc < nchunk; kc++) {
        CP_WAIT0();
        __syncthreads();
        if (kc + 1 < nchunk) prefetch(kc + 1, (kc + 1) & 1);
        CP_COMMIT();

        uint32_t bo = base + (kc & 1) * BUFSZ;
#pragma unroll
        for (int kk = 0; kk < 2; kk++) {
            uint32_t kb = kk * 32;
            uint32_t bh4[2][4];
#pragma unroll
            for (int p = 0; p < 2; p++)
                ldsm4(bh4[p], bo + ASZ + bOff4 + p * 16 * ROWB + kb);
#pragma unroll
            for (int mt = 0; mt < MT; mt++) {
                uint32_t ah[4];
                ldsm4(ah, bo + aOff + mt * 16 * ROWB + kb);
#pragma unroll
                for (int nt = 0; nt < 4; nt++)
                    mma_f16(acc[mt][nt], ah, &bh4[nt >> 1][(nt & 1) * 2]);
            }
        }
    }

    int er = m0 + wm + (lane >> 2);
    int ec = n0 + wn + (lane & 3) * 2;
#pragma unroll
    for (int mt = 0; mt < MT; mt++) {
#pragma unroll
        for (int nt = 0; nt < 4; nt++) {
            int col = ec + nt * 8;
            if (col >= Nlim) continue;
            float* p0 = C + (size_t)(er + mt * 16) * ldc + col;
            float* p1 = p0 + 8 * ldc;
            float d0 = acc[mt][nt][0], d1 = acc[mt][nt][1];
            float d2 = acc[mt][nt][2], d3 = acc[mt][nt][3];
            if (EPI == 3) {
                atomicAdd(p0, d0); atomicAdd(p0 + 1, d1);
                atomicAdd(p1, d2); atomicAdd(p1 + 1, d3);
                continue;
            }
            if (EPI == 1) {
                float b0 = aux[col], b1 = aux[col + 1];
                d0 += b0; d1 += b1; d2 += b0; d3 += b1;
                d0 = (d0 > 20.f) ? d0 : log1pf(__expf(d0));
                d1 = (d1 > 20.f) ? d1 : log1pf(__expf(d1));
                d2 = (d2 > 20.f) ? d2 : log1pf(__expf(d2));
                d3 = (d3 > 20.f) ? d3 : log1pf(__expf(d3));
            } else if (EPI == 2) {
                float2 o0 = *(float2*)p0, o1 = *(float2*)p1;
                d0 += o0.x; d1 += o0.y; d2 += o1.x; d3 += o1.y;
            }
            *(float2*)p0 = make_float2(d0, d1);
            *(float2*)p1 = make_float2(d2, d3);
        }
    }
}

// ---------------- selective scan ----------------
__global__ void scan1_k(const float* __restrict__ delta, const float* __restrict__ xb,
                        const float* __restrict__ dbc, const float* __restrict__ A_log,
                        float* __restrict__ cp, float* __restrict__ cs) {
    int i = blockIdx.x * blockDim.x + threadIdx.x;
    if (i >= NCHUNK * ED) return;
    int c = i / ED, e = i % ED;
    float A[NST], h[NST], p[NST];
#pragma unroll
    for (int n = 0; n < NST; n++) {
        A[n] = -__expf(A_log[e * NST + n]);
        h[n] = 0.f; p[n] = 1.f;
    }
    int t0 = c * CHUNK;
    for (int t = t0; t < t0 + CHUNK; t++) {
        float d  = delta[(size_t)t * ED + e];
        float xv = xb[(size_t)t * ED + e];
        float dx = d * xv;
        const float* Bt = dbc + (size_t)t * DXP + DTR;
#pragma unroll
        for (int n = 0; n < NST; n++) {
            float a = __expf(d * A[n]);
            p[n] *= a;
            h[n] = fmaf(a, h[n], dx * Bt[n]);
        }
    }
    size_t o = (size_t)i * NST;
#pragma unroll
    for (int n = 0; n < NST; n++) { cp[o + n] = p[n]; cs[o + n] = h[n]; }
}

__global__ void carry_k(const float* __restrict__ cp, const float* __restrict__ cs,
                        float* __restrict__ cc) {
    int i = blockIdx.x * blockDim.x + threadIdx.x;
    if (i >= ED * NST) return;
    float H = 0.f;
    for (int c = 0; c < NCHUNK; c++) {
        size_t idx = (size_t)c * ED * NST + i;
        cc[idx] = H;
        H = fmaf(cp[idx], H, cs[idx]);
    }
}

__global__ void scan2_k(const float* __restrict__ delta, const float* __restrict__ xb,
                        const float* __restrict__ dbc, const float* __restrict__ A_log,
                        const float* __restrict__ cc, const float* __restrict__ Dp,
                        const float* __restrict__ xz,
                        __half* __restrict__ yzh) {
    int i = blockIdx.x * blockDim.x + threadIdx.x;
    if (i >= NCHUNK * ED) return;
    int c = i / ED, e = i % ED;
    float A[NST], h[NST];
#pragma unroll
    for (int n = 0; n < NST; n++) {
        A[n] = -__expf(A_log[e * NST + n]);
        h[n] = cc[(size_t)i * NST + n];
    }
    float Dv = Dp[e];
    int t0 = c * CHUNK;
    for (int t = t0; t < t0 + CHUNK; t++) {
        float d  = delta[(size_t)t * ED + e];
        float xv = xb[(size_t)t * ED + e];
        float dx = d * xv;
        const float* Bt = dbc + (size_t)t * DXP + DTR;
        const float* Ct = dbc + (size_t)t * DXP + DTR + NST;
        float y = 0.f;
#pragma unroll
        for (int n = 0; n < NST; n++) {
            float a = __expf(d * A[n]);
            h[n] = fmaf(a, h[n], dx * Bt[n]);
            y = fmaf(h[n], Ct[n], y);
        }
        float zv = xz[(size_t)t * (2 * ED) + ED + e];
        float sz = zv / (1.f + __expf(-zv));
        yzh[(size_t)t * ED + e] = __float2half_rn((y + xv * Dv) * sz);
    }
}

// ---------------- host orchestration ----------------
extern "C" void kernel_launch(void* const* d_in, const int* in_sizes, int n_in,
                              void* d_out, int out_size) {
    const int*   tokens  = (const int*)d_in[0];
    const float* emb     = (const float*)d_in[1];
    const float* norm_w  = (const float*)d_in[2];
    const float* in_proj = (const float*)d_in[3];
    const float* conv_w  = (const float*)d_in[4];
    const float* conv_b  = (const float*)d_in[5];
    const float* x_proj  = (const float*)d_in[6];
    const float* dt_w    = (const float*)d_in[7];
    const float* dt_b    = (const float*)d_in[8];
    const float* A_log   = (const float*)d_in[9];
    const float* Dp      = (const float*)d_in[10];
    const float* out_prj = (const float*)d_in[11];
    const float* norm_f  = (const float*)d_in[12];
    const float* lm_head = (const float*)d_in[13];
    float* logits = (float*)d_out;

    float *x, *xz, *xb, *dbc, *delta, *cp, *cs, *cc;
    __half *ah, *dh, *wh;
    cudaGetSymbolAddress((void**)&x,     g_x);
    cudaGetSymbolAddress((void**)&xz,    g_xz);
    cudaGetSymbolAddress((void**)&xb,    g_xb);
    cudaGetSymbolAddress((void**)&dbc,   g_dbc);
    cudaGetSymbolAddress((void**)&delta, g_delta);
    cudaGetSymbolAddress((void**)&cp,    g_cp);
    cudaGetSymbolAddress((void**)&cs,    g_cs);
    cudaGetSymbolAddress((void**)&cc,    g_cc);
    cudaGetSymbolAddress((void**)&ah,    g_ah);
    cudaGetSymbolAddress((void**)&dh,    g_dh);
    cudaGetSymbolAddress((void**)&wh,    g_wh);

    const int SM4 = 2 * (4 * 32 * ROWB + 128 * ROWB);   // 40960
    const int SM2 = 2 * (2 * 32 * ROWB + 128 * ROWB);   // 30720
    const int SM1 = 2 * (1 * 32 * ROWB + 128 * ROWB);   // 25600
    static bool attr_done = false;
    if (!attr_done) {
        cudaFuncSetAttribute(h1gemm_k<2,0>, cudaFuncAttributeMaxDynamicSharedMemorySize, SM2);
        cudaFuncSetAttribute(h1gemm_k<2,2>, cudaFuncAttributeMaxDynamicSharedMemorySize, SM2);
        cudaFuncSetAttribute(h1gemm_k<1,3>, cudaFuncAttributeMaxDynamicSharedMemorySize, SM1);
        cudaFuncSetAttribute(h1gemm_k<4,1>, cudaFuncAttributeMaxDynamicSharedMemorySize, SM4);
        cudaFuncSetAttribute(h1gemm_k<4,0>, cudaFuncAttributeMaxDynamicSharedMemorySize, SM4);
        attr_done = true;
    }

    embed_k<<<(L * D + 255) / 256, 256>>>(tokens, emb, x);

    for (int l = 0; l < NL; l++) {
        rmsnorm_h_k<<<L, 256>>>(x, norm_w + l * D, ah);

        // xz = xn @ in_proj^T
        int nwi = 2 * ED * D;
        tofp16_k<<<(nwi / 4 + 255) / 256, 256>>>(
            (const float4*)(in_proj + (size_t)l * nwi), (__half2*)wh, nwi / 4);
        h1gemm_k<2,0><<<dim3(L / 64, 2 * ED / 128), 256, SM2>>>(
            ah, wh, xz, D, D, 2 * ED, 2 * ED, nullptr);

        // conv + silu (also emits fp16 xb into ah)
        conv_silu_h_k<<<(L * ED + 255) / 256, 256>>>(
            xz, conv_w + (size_t)l * ED * DCONV, conv_b + l * ED, xb, ah);

        // dbc = xb @ x_proj^T  (N=80 padded to 128, split-K=2 with atomics)
        tofp16_pad_k<<<(128 * ED + 255) / 256, 256>>>(
            x_proj + (size_t)l * DXP * ED, wh, 128, ED, DXP, ED, ED);
        cudaMemsetAsync(dbc, 0, (size_t)L * DXP * sizeof(float));
        h1gemm_k<1,3><<<dim3(L / 32, 1, 2), 256, SM1>>>(
            ah, wh, dbc, ED / 2, ED, DXP, DXP, nullptr);

        // delta = softplus(dbc[:, :48] @ dt_w^T + dt_b)   (K=48 padded to 64)
        tofp16_pad_k<<<(L * 64 + 255) / 256, 256>>>(dbc, dh, L, 64, L, DTR, DXP);
        tofp16_pad_k<<<(ED * 64 + 255) / 256, 256>>>(
            dt_w + (size_t)l * ED * DTR, wh, ED, 64, ED, DTR, DTR);
        h1gemm_k<4,1><<<dim3(L / 128, ED / 128), 256, SM4>>>(
            dh, wh, delta, 64, 64, ED, ED, dt_b + l * ED);

        // selective scan (writes gated output as fp16 into ah)
        scan1_k<<<(NCHUNK * ED) / 256, 256>>>(delta, xb, dbc,
                                              A_log + (size_t)l * ED * NST, cp, cs);
        carry_k<<<(ED * NST) / 256, 256>>>(cp, cs, cc);
        scan2_k<<<(NCHUNK * ED) / 256, 256>>>(delta, xb, dbc,
                                              A_log + (size_t)l * ED * NST, cc,
                                              Dp + l * ED, xz, ah);

        // x += yz @ out_proj^T
        int nwo = D * ED;
        tofp16_k<<<(nwo / 4 + 255) / 256, 256>>>(
            (const float4*)(out_prj + (size_t)l * nwo), (__half2*)wh, nwo / 4);
        h1gemm_k<2,2><<<dim3(L / 64, D / 128), 256, SM2>>>(
            ah, wh, x, ED, ED, D, D, nullptr);
    }

    // final norm + lm_head (1-term fp16)
    rmsnorm_h_k<<<L, 256>>>(x, norm_f, ah);
    int nwl = VOCAB * D;
    tofp16_k<<<(nwl / 4 + 255) / 256, 256>>>(
        (const float4*)lm_head, (__half2*)wh, nwl / 4);
    h1gemm_k<4,0><<<dim3(L / 128, VOCAB / 128), 256, SM4>>>(
        ah, wh, logits, D, D, VOCAB, VOCAB, nullptr);
}

// round 12
// speedup vs baseline: 2.6600x; 1.0101x over previous
#include <cuda_runtime.h>
#include <cuda_bf16.h>
#include <cuda_fp16.h>
#include <math.h>
#include <cstdint>

// ---------------- problem constants ----------------
#define L       2048
#define D       768
#define ED      1536
#define NL      4
#define NST     16
#define DTR     48
#define DXP     80
#define VOCAB   32000
#define DCONV   4
#define CHUNK   64
#define NCHUNK  (L / CHUNK)

// ---------------- scratch ----------------
__device__ __align__(256) float g_x    [L * D];
__device__ __align__(256) float g_xz   [L * 2 * ED];
__device__ __align__(256) float g_xb   [L * ED];
__device__ __align__(256) float g_dbc  [L * DXP];
__device__ __align__(256) float g_delta[L * ED];
__device__ __align__(256) float g_cp   [NCHUNK * ED * NST];
__device__ __align__(256) float g_cs   [NCHUNK * ED * NST];
__device__ __align__(256) float g_cc   [NCHUNK * ED * NST];
__device__ __align__(256) __half g_ah[L * ED];
__device__ __align__(256) __half g_dh[L * 64];
__device__ __align__(256) __half g_wh[VOCAB * D];

// ---------------- helpers ----------------
__device__ __forceinline__ uint32_t smem_u32(const void* p) {
    uint32_t a;
    asm("{ .reg .u64 t; cvta.to.shared.u64 t, %1; cvt.u32.u64 %0, t; }" : "=r"(a) : "l"(p));
    return a;
}
__device__ __forceinline__ void ldsm4(uint32_t* r, uint32_t addr) {
    asm volatile("ldmatrix.sync.aligned.m8n8.x4.shared.b16 {%0,%1,%2,%3}, [%4];"
                 : "=r"(r[0]), "=r"(r[1]), "=r"(r[2]), "=r"(r[3]) : "r"(addr));
}
__device__ __forceinline__ void mma_f16(float* d, const uint32_t* a, const uint32_t* b) {
    asm volatile(
        "mma.sync.aligned.m16n8k16.row.col.f32.f16.f16.f32 "
        "{%0,%1,%2,%3}, {%4,%5,%6,%7}, {%8,%9}, {%0,%1,%2,%3};"
        : "+f"(d[0]), "+f"(d[1]), "+f"(d[2]), "+f"(d[3])
        : "r"(a[0]), "r"(a[1]), "r"(a[2]), "r"(a[3]), "r"(b[0]), "r"(b[1]));
}
__device__ __forceinline__ void cpa16(uint32_t d, const void* s) {
    asm volatile("cp.async.cg.shared.global [%0], [%1], 16;" :: "r"(d), "l"(s));
}
#define CP_COMMIT() asm volatile("cp.async.commit_group;" ::: "memory")
#define CP_WAIT1()  asm volatile("cp.async.wait_group 1;" ::: "memory")

// ---------------- embedding ----------------
__global__ void embed_k(const int* __restrict__ tok, const float* __restrict__ emb,
                        float* __restrict__ x) {
    int i = blockIdx.x * blockDim.x + threadIdx.x;
    if (i >= L * D) return;
    int t = i / D, d = i % D;
    x[i] = emb[(size_t)tok[t] * D + d];
}

// ---------------- fp32 -> fp16 flat convert ----------------
__global__ void tofp16_k(const float4* __restrict__ src, __half2* __restrict__ dst, int n4) {
    int i = blockIdx.x * blockDim.x + threadIdx.x;
    if (i >= n4) return;
    float4 v = src[i];
    dst[2 * i]     = __floats2half2_rn(v.x, v.y);
    dst[2 * i + 1] = __floats2half2_rn(v.z, v.w);
}

// fp32 -> fp16 padded convert
__global__ void tofp16_pad_k(const float* __restrict__ src, __half* __restrict__ dst,
                             int Mdst, int Kp, int Msrc, int Kin, int Ssrc) {
    int i = blockIdx.x * blockDim.x + threadIdx.x;
    if (i >= Mdst * Kp) return;
    int r = i / Kp, c = i % Kp;
    float v = (r < Msrc && c < Kin) ? src[(size_t)r * Ssrc + c] : 0.f;
    dst[i] = __float2half_rn(v);
}

// ---------------- RMSNorm -> fp16 ----------------
__global__ void rmsnorm_h_k(const float* __restrict__ x, const float* __restrict__ w,
                            __half* __restrict__ oh) {
    int t = blockIdx.x;
    const float* xr = x + (size_t)t * D;
    float s = 0.f;
    for (int d = threadIdx.x; d < D; d += 256) { float v = xr[d]; s += v * v; }
    __shared__ float red[256];
    red[threadIdx.x] = s;
    __syncthreads();
    for (int o = 128; o > 0; o >>= 1) {
        if (threadIdx.x < o) red[threadIdx.x] += red[threadIdx.x + o];
        __syncthreads();
    }
    float inv = rsqrtf(red[0] / (float)D + 1e-5f);
    for (int d = threadIdx.x; d < D; d += 256)
        oh[(size_t)t * D + d] = __float2half_rn(xr[d] * inv * w[d]);
}

// ---------------- conv1d + silu -> fp32 + fp16 ----------------
__global__ void conv_silu_h_k(const float* __restrict__ xz, const float* __restrict__ w,
                              const float* __restrict__ b, float* __restrict__ xb,
                              __half* __restrict__ oh) {
    int i = blockIdx.x * blockDim.x + threadIdx.x;
    if (i >= L * ED) return;
    int t = i / ED, e = i % ED;
    const float* wr = w + e * DCONV;
    float acc = b[e];
#pragma unroll
    for (int j = 0; j < DCONV; j++) {
        int tt = t - (DCONV - 1) + j;
        if (tt >= 0) acc = fmaf(xz[(size_t)tt * (2 * ED) + e], wr[j], acc);
    }
    float v = acc / (1.f + __expf(-acc));
    xb[i] = v;
    oh[i] = __float2half_rn(v);
}

// ---------------- fp16 1-term GEMM, 3-stage pipeline, chunk-wide frag preload ----
// C[(MT*32) x 128] tile. C = A * B^T (fp32 accum).
// EPI: 0 = store, 1 = softplus(acc + aux[n]), 2 = C += acc, 3 = atomicAdd (split-K).
#define ROWB 80

template<int MT, int EPI>
__global__ __launch_bounds__(256, 2) void h1gemm_k(
    const __half* __restrict__ A, const __half* __restrict__ B,
    float* __restrict__ C, int K, int strideK, int ldc, int Nlim,
    const float* __restrict__ aux)
{
    constexpr int ASZ   = MT * 32 * ROWB;
    constexpr int BSZ   = 128 * ROWB;
    constexpr int BUFSZ = ASZ + BSZ;

    extern __shared__ char dynsm[];
    uint32_t base = smem_u32(dynsm);

    int tid = threadIdx.x, lane = tid & 31, wid = tid >> 5;
    int m0 = blockIdx.x * (MT * 32), n0 = blockIdx.y * 128;
    int wm = (wid & 1) * (MT * 16), wn = (wid >> 1) * 32;
    int koff = blockIdx.z * K;

    int lr = tid >> 2;
    int lk = (tid & 3) * 8;

    const __half* gA0 = A + (size_t)(m0 + lr) * strideK + koff + lk;
    const __half* gA1 = (MT == 4) ? gA0 + (size_t)64 * strideK : gA0;
    const __half* gB0 = B + (size_t)(n0 + lr) * strideK + koff + lk;
    const __half* gB1 = gB0 + (size_t)64 * strideK;

    uint32_t st0 = (uint32_t)(lr * ROWB + lk * 2);
    uint32_t st1 = st0 + 64 * ROWB;

    uint32_t aOff = (uint32_t)((wm + (lane & 15)) * ROWB + (lane >> 4) * 16);
    uint32_t bOff4 = (uint32_t)((wn + ((lane >> 4) << 3) + (lane & 7)) * ROWB
                                + ((lane >> 3) & 1) * 16);

    float acc[MT][4][4];
#pragma unroll
    for (int i = 0; i < MT; i++)
#pragma unroll
        for (int j = 0; j < 4; j++)
#pragma unroll
            for (int r = 0; r < 4; r++) acc[i][j][r] = 0.f;

    int nchunk = K >> 5;

    auto prefetch = [&](int kc, int buf) {
        int ko = kc * 32;
        uint32_t bo = base + buf * BUFSZ;
        if (MT == 4) {
            cpa16(bo + st0, gA0 + ko);
            cpa16(bo + st1, gA1 + ko);
        } else if (MT == 2) {
            cpa16(bo + st0, gA0 + ko);
        } else {
            if (lr < 32) cpa16(bo + st0, gA0 + ko);
        }
        cpa16(bo + ASZ + st0, gB0 + ko);
        cpa16(bo + ASZ + st1, gB1 + ko);
    };

    // 3-stage: stages kc and kc+1 in flight during compute of kc
    prefetch(0, 0); CP_COMMIT();
    if (nchunk > 1) prefetch(1, 1);
    CP_COMMIT();

    int buf = 0;
    for (int kc = 0; kc < nchunk; kc++) {
        CP_WAIT1();              // stage kc resident (kc+1 may be in flight)
        __syncthreads();         // publish stage kc; prior readers of buf(kc+2)%3 done
        if (kc + 2 < nchunk) prefetch(kc + 2, (kc + 2) % 3);
        CP_COMMIT();

        uint32_t bo = base + buf * BUFSZ;
        buf = (buf + 1 == 3) ? 0 : buf + 1;

        // chunk-wide B fragment preload (both kk-steps)
        uint32_t bh4[2][2][4];
#pragma unroll
        for (int kk = 0; kk < 2; kk++)
#pragma unroll
            for (int p = 0; p < 2; p++)
                ldsm4(bh4[kk][p], bo + ASZ + bOff4 + p * 16 * ROWB + kk * 32);

        if (MT <= 2) {
            // A fragments for both kk as well — max ILP
            uint32_t af[2][MT][4];
#pragma unroll
            for (int kk = 0; kk < 2; kk++)
#pragma unroll
                for (int mt = 0; mt < MT; mt++)
                    ldsm4(af[kk][mt], bo + aOff + mt * 16 * ROWB + kk * 32);
#pragma unroll
            for (int kk = 0; kk < 2; kk++)
#pragma unroll
                for (int mt = 0; mt < MT; mt++)
#pragma unroll
                    for (int nt = 0; nt < 4; nt++)
                        mma_f16(acc[mt][nt], af[kk][mt], &bh4[kk][nt >> 1][(nt & 1) * 2]);
        } else {
#pragma unroll
            for (int kk = 0; kk < 2; kk++)
#pragma unroll
                for (int mt = 0; mt < MT; mt++) {
                    uint32_t ah[4];
                    ldsm4(ah, bo + aOff + mt * 16 * ROWB + kk * 32);
#pragma unroll
                    for (int nt = 0; nt < 4; nt++)
                        mma_f16(acc[mt][nt], ah, &bh4[kk][nt >> 1][(nt & 1) * 2]);
                }
        }
    }

    int er = m0 + wm + (lane >> 2);
    int ec = n0 + wn + (lane & 3) * 2;
#pragma unroll
    for (int mt = 0; mt < MT; mt++) {
#pragma unroll
        for (int nt = 0; nt < 4; nt++) {
            int col = ec + nt * 8;
            if (col >= Nlim) continue;
            float* p0 = C + (size_t)(er + mt * 16) * ldc + col;
            float* p1 = p0 + 8 * ldc;
            float d0 = acc[mt][nt][0], d1 = acc[mt][nt][1];
            float d2 = acc[mt][nt][2], d3 = acc[mt][nt][3];
            if (EPI == 3) {
                atomicAdd(p0, d0); atomicAdd(p0 + 1, d1);
                atomicAdd(p1, d2); atomicAdd(p1 + 1, d3);
                continue;
            }
            if (EPI == 1) {
                float b0 = aux[col], b1 = aux[col + 1];
                d0 += b0; d1 += b1; d2 += b0; d3 += b1;
                d0 = (d0 > 20.f) ? d0 : log1pf(__expf(d0));
                d1 = (d1 > 20.f) ? d1 : log1pf(__expf(d1));
                d2 = (d2 > 20.f) ? d2 : log1pf(__expf(d2));
                d3 = (d3 > 20.f) ? d3 : log1pf(__expf(d3));
            } else if (EPI == 2) {
                float2 o0 = *(float2*)p0, o1 = *(float2*)p1;
                d0 += o0.x; d1 += o0.y; d2 += o1.x; d3 += o1.y;
            }
            *(float2*)p0 = make_float2(d0, d1);
            *(float2*)p1 = make_float2(d2, d3);
        }
    }
}

// ---------------- selective scan ----------------
__global__ void scan1_k(const float* __restrict__ delta, const float* __restrict__ xb,
                        const float* __restrict__ dbc, const float* __restrict__ A_log,
                        float* __restrict__ cp, float* __restrict__ cs) {
    int i = blockIdx.x * blockDim.x + threadIdx.x;
    if (i >= NCHUNK * ED) return;
    int c = i / ED, e = i % ED;
    float A[NST], h[NST], p[NST];
#pragma unroll
    for (int n = 0; n < NST; n++) {
        A[n] = -__expf(A_log[e * NST + n]);
        h[n] = 0.f; p[n] = 1.f;
    }
    int t0 = c * CHUNK;
    for (int t = t0; t < t0 + CHUNK; t++) {
        float d  = delta[(size_t)t * ED + e];
        float xv = xb[(size_t)t * ED + e];
        float dx = d * xv;
        const float* Bt = dbc + (size_t)t * DXP + DTR;
#pragma unroll
        for (int n = 0; n < NST; n++) {
            float a = __expf(d * A[n]);
            p[n] *= a;
            h[n] = fmaf(a, h[n], dx * Bt[n]);
        }
    }
    size_t o = (size_t)i * NST;
#pragma unroll
    for (int n = 0; n < NST; n++) { cp[o + n] = p[n]; cs[o + n] = h[n]; }
}

__global__ void carry_k(const float* __restrict__ cp, const float* __restrict__ cs,
                        float* __restrict__ cc) {
    int i = blockIdx.x * blockDim.x + threadIdx.x;
    if (i >= ED * NST) return;
    float H = 0.f;
    for (int c = 0; c < NCHUNK; c++) {
        size_t idx = (size_t)c * ED * NST + i;
        cc[idx] = H;
        H = fmaf(cp[idx], H, cs[idx]);
    }
}

__global__ void scan2_k(const float* __restrict__ delta, const float* __restrict__ xb,
                        const float* __restrict__ dbc, const float* __restrict__ A_log,
                        const float* __restrict__ cc, const float* __restrict__ Dp,
                        const float* __restrict__ xz,
                        __half* __restrict__ yzh) {
    int i = blockIdx.x * blockDim.x + threadIdx.x;
    if (i >= NCHUNK * ED) return;
    int c = i / ED, e = i % ED;
    float A[NST], h[NST];
#pragma unroll
    for (int n = 0; n < NST; n++) {
        A[n] = -__expf(A_log[e * NST + n]);
        h[n] = cc[(size_t)i * NST + n];
    }
    float Dv = Dp[e];
    int t0 = c * CHUNK;
    for (int t = t0; t < t0 + CHUNK; t++) {
        float d  = delta[(size_t)t * ED + e];
        float xv = xb[(size_t)t * ED + e];
        float dx = d * xv;
        const float* Bt = dbc + (size_t)t * DXP + DTR;
        const float* Ct = dbc + (size_t)t * DXP + DTR + NST;
        float y = 0.f;
#pragma unroll
        for (int n = 0; n < NST; n++) {
            float a = __expf(d * A[n]);
            h[n] = fmaf(a, h[n], dx * Bt[n]);
            y = fmaf(h[n], Ct[n], y);
        }
        float zv = xz[(size_t)t * (2 * ED) + ED + e];
        float sz = zv / (1.f + __expf(-zv));
        yzh[(size_t)t * ED + e] = __float2half_rn((y + xv * Dv) * sz);
    }
}

// ---------------- host orchestration ----------------
extern "C" void kernel_launch(void* const* d_in, const int* in_sizes, int n_in,
                              void* d_out, int out_size) {
    const int*   tokens  = (const int*)d_in[0];
    const float* emb     = (const float*)d_in[1];
    const float* norm_w  = (const float*)d_in[2];
    const float* in_proj = (const float*)d_in[3];
    const float* conv_w  = (const float*)d_in[4];
    const float* conv_b  = (const float*)d_in[5];
    const float* x_proj  = (const float*)d_in[6];
    const float* dt_w    = (const float*)d_in[7];
    const float* dt_b    = (const float*)d_in[8];
    const float* A_log   = (const float*)d_in[9];
    const float* Dp      = (const float*)d_in[10];
    const float* out_prj = (const float*)d_in[11];
    const float* norm_f  = (const float*)d_in[12];
    const float* lm_head = (const float*)d_in[13];
    float* logits = (float*)d_out;

    float *x, *xz, *xb, *dbc, *delta, *cp, *cs, *cc;
    __half *ah, *dh, *wh;
    cudaGetSymbolAddress((void**)&x,     g_x);
    cudaGetSymbolAddress((void**)&xz,    g_xz);
    cudaGetSymbolAddress((void**)&xb,    g_xb);
    cudaGetSymbolAddress((void**)&dbc,   g_dbc);
    cudaGetSymbolAddress((void**)&delta, g_delta);
    cudaGetSymbolAddress((void**)&cp,    g_cp);
    cudaGetSymbolAddress((void**)&cs,    g_cs);
    cudaGetSymbolAddress((void**)&cc,    g_cc);
    cudaGetSymbolAddress((void**)&ah,    g_ah);
    cudaGetSymbolAddress((void**)&dh,    g_dh);
    cudaGetSymbolAddress((void**)&wh,    g_wh);

    const int SM4 = 3 * (4 * 32 * ROWB + 128 * ROWB);   // 61440
    const int SM2 = 3 * (2 * 32 * ROWB + 128 * ROWB);   // 46080
    const int SM1 = 3 * (1 * 32 * ROWB + 128 * ROWB);   // 38400
    static bool attr_done = false;
    if (!attr_done) {
        cudaFuncSetAttribute(h1gemm_k<2,0>, cudaFuncAttributeMaxDynamicSharedMemorySize, SM2);
        cudaFuncSetAttribute(h1gemm_k<2,2>, cudaFuncAttributeMaxDynamicSharedMemorySize, SM2);
        cudaFuncSetAttribute(h1gemm_k<1,3>, cudaFuncAttributeMaxDynamicSharedMemorySize, SM1);
        cudaFuncSetAttribute(h1gemm_k<4,1>, cudaFuncAttributeMaxDynamicSharedMemorySize, SM4);
        cudaFuncSetAttribute(h1gemm_k<4,0>, cudaFuncAttributeMaxDynamicSharedMemorySize, SM4);
        attr_done = true;
    }

    embed_k<<<(L * D + 255) / 256, 256>>>(tokens, emb, x);

    for (int l = 0; l < NL; l++) {
        rmsnorm_h_k<<<L, 256>>>(x, norm_w + l * D, ah);

        // xz = xn @ in_proj^T
        int nwi = 2 * ED * D;
        tofp16_k<<<(nwi / 4 + 255) / 256, 256>>>(
            (const float4*)(in_proj + (size_t)l * nwi), (__half2*)wh, nwi / 4);
        h1gemm_k<2,0><<<dim3(L / 64, 2 * ED / 128), 256, SM2>>>(
            ah, wh, xz, D, D, 2 * ED, 2 * ED, nullptr);

        // conv + silu (also emits fp16 xb into ah)
        conv_silu_h_k<<<(L * ED + 255) / 256, 256>>>(
            xz, conv_w + (size_t)l * ED * DCONV, conv_b + l * ED, xb, ah);

        // dbc = xb @ x_proj^T  (N=80 padded to 128, split-K=2 with atomics)
        tofp16_pad_k<<<(128 * ED + 255) / 256, 256>>>(
            x_proj + (size_t)l * DXP * ED, wh, 128, ED, DXP, ED, ED);
        cudaMemsetAsync(dbc, 0, (size_t)L * DXP * sizeof(float));
        h1gemm_k<1,3><<<dim3(L / 32, 1, 2), 256, SM1>>>(
            ah, wh, dbc, ED / 2, ED, DXP, DXP, nullptr);

        // delta = softplus(dbc[:, :48] @ dt_w^T + dt_b)   (K=48 padded to 64)
        tofp16_pad_k<<<(L * 64 + 255) / 256, 256>>>(dbc, dh, L, 64, L, DTR, DXP);
        tofp16_pad_k<<<(ED * 64 + 255) / 256, 256>>>(
            dt_w + (size_t)l * ED * DTR, wh, ED, 64, ED, DTR, DTR);
        h1gemm_k<4,1><<<dim3(L / 128, ED / 128), 256, SM4>>>(
            dh, wh, delta, 64, 64, ED, ED, dt_b + l * ED);

        // selective scan (writes gated output as fp16 into ah)
        scan1_k<<<(NCHUNK * ED) / 256, 256>>>(delta, xb, dbc,
                                              A_log + (size_t)l * ED * NST, cp, cs);
        carry_k<<<(ED * NST) / 256, 256>>>(cp, cs, cc);
        scan2_k<<<(NCHUNK * ED) / 256, 256>>>(delta, xb, dbc,
                                              A_log + (size_t)l * ED * NST, cc,
                                              Dp + l * ED, xz, ah);

        // x += yz @ out_proj^T
        int nwo = D * ED;
        tofp16_k<<<(nwo / 4 + 255) / 256, 256>>>(
            (const float4*)(out_prj + (size_t)l * nwo), (__half2*)wh, nwo / 4);
        h1gemm_k<2,2><<<dim3(L / 64, D / 128), 256, SM2>>>(
            ah, wh, x, ED, ED, D, D, nullptr);
    }

    // final norm + lm_head
    rmsnorm_h_k<<<L, 256>>>(x, norm_f, ah);
    int nwl = VOCAB * D;
    tofp16_k<<<(nwl / 4 + 255) / 256, 256>>>(
        (const float4*)lm_head, (__half2*)wh, nwl / 4);
    h1gemm_k<4,0><<<dim3(L / 128, VOCAB / 128), 256, SM4>>>(
        ah, wh, logits, D, D, VOCAB, VOCAB, nullptr);
}